// round 2
// baseline (speedup 1.0000x reference)
#include <cuda_runtime.h>

// Problem constants (fixed shapes)
#define BB   2
#define NN   2048
#define DD   768
#define HH   12
#define DH   64
#define DP   192
#define NPOS 4095   // 2*N - 1

#define ATT_STRIDE 68  // padded smem row stride (floats) for 64-wide tiles

// ---------------- scratch (device globals; no allocations allowed) ------------
__device__ float g_q[(size_t)BB*HH*NN*DH];     // [b,h,n,d], pre-scaled by 1/8
__device__ float g_k[(size_t)BB*HH*NN*DH];
__device__ float g_v[(size_t)BB*HH*NN*DH];
__device__ float g_vals[(size_t)NPOS*HH];      // DPB MLP output [2N-1, H]
__device__ float g_o[(size_t)BB*NN*DD];        // attention output [b,n,h*64+d]

// =============================================================================
// Kernel 1: QKV projection GEMM.  X[4096,768] @ W[768,2304] + b
// Epilogue scatters into g_q/g_k/g_v with [b,h,n,d] layout; q scaled by 0.125.
// 64x64 tile, BK=16, 256 threads, 4x4 per thread.
// =============================================================================
__global__ __launch_bounds__(256) void qkv_gemm(const float* __restrict__ X,
                                                const float* __restrict__ W,
                                                const float* __restrict__ bias)
{
    __shared__ float As[16][ATT_STRIDE];   // transposed: As[k][m]
    __shared__ float Bs[16][ATT_STRIDE];   // natural:    Bs[k][n]
    const int bm = blockIdx.y * 64;
    const int bn = blockIdx.x * 64;
    const int tid = threadIdx.x;
    const int tx = tid & 15, ty = tid >> 4;
    const int ar = tid >> 2, ac = (tid & 3) << 2;
    const int br = tid >> 4, bc = (tid & 15) << 2;

    float acc[4][4] = {};
    for (int k0 = 0; k0 < 768; k0 += 16) {
        float4 a = *reinterpret_cast<const float4*>(&X[(size_t)(bm + ar) * 768 + k0 + ac]);
        As[ac + 0][ar] = a.x; As[ac + 1][ar] = a.y;
        As[ac + 2][ar] = a.z; As[ac + 3][ar] = a.w;
        *reinterpret_cast<float4*>(&Bs[br][bc]) =
            *reinterpret_cast<const float4*>(&W[(size_t)(k0 + br) * 2304 + bn + bc]);
        __syncthreads();
#pragma unroll
        for (int kk = 0; kk < 16; kk++) {
            float4 av = *reinterpret_cast<const float4*>(&As[kk][ty * 4]);
            float4 bv = *reinterpret_cast<const float4*>(&Bs[kk][tx * 4]);
            float aa[4] = {av.x, av.y, av.z, av.w};
            float bb2[4] = {bv.x, bv.y, bv.z, bv.w};
#pragma unroll
            for (int i = 0; i < 4; i++)
#pragma unroll
                for (int j = 0; j < 4; j++)
                    acc[i][j] = fmaf(aa[i], bb2[j], acc[i][j]);
        }
        __syncthreads();
    }

    const int col0 = bn + tx * 4;
    const int t   = col0 / 768;       // 0=q, 1=k, 2=v  (64-col tiles never straddle)
    const int rem = col0 - t * 768;
    const int h   = rem >> 6;
    const int d0  = rem & 63;
    float* dst = (t == 0) ? g_q : (t == 1) ? g_k : g_v;
    const float sc = (t == 0) ? 0.125f : 1.0f;   // Dh^-0.5 folded into q
    float4 bz = *reinterpret_cast<const float4*>(&bias[col0]);
#pragma unroll
    for (int i = 0; i < 4; i++) {
        int row = bm + ty * 4 + i;
        int b = row >> 11, n = row & 2047;
        float4 o;
        o.x = (acc[i][0] + bz.x) * sc;
        o.y = (acc[i][1] + bz.y) * sc;
        o.z = (acc[i][2] + bz.z) * sc;
        o.w = (acc[i][3] + bz.w) * sc;
        *reinterpret_cast<float4*>(&dst[(((size_t)b * HH + h) * NN + n) * DH + d0]) = o;
    }
}

// =============================================================================
// Kernel 2: DynamicPositionBias MLP, fully fused.  16 rows per block, 192 thr.
// tmp = pre-activation; LN+SiLU -> hbuf; GEMM -> tmp; out layer -> g_vals.
// =============================================================================
__global__ __launch_bounds__(192) void dpb_kernel(const float* __restrict__ w_in,
                                                  const float* __restrict__ b_in,
                                                  const float* __restrict__ w_hid,
                                                  const float* __restrict__ b_hid,
                                                  const float* __restrict__ ln_g,
                                                  const float* __restrict__ ln_b,
                                                  const float* __restrict__ w_out,
                                                  const float* __restrict__ b_out)
{
    __shared__ float hbuf[16][DP];
    __shared__ float tmp[16][DP];
    __shared__ float mu_s[16], rs_s[16];
    const int j    = threadIdx.x;         // 0..191
    const int r0   = blockIdx.x * 16;
    const int warp = j >> 5, lane = j & 31;

    // input layer pre-activation: signed-log positions * w_in + b_in
    const float wi = w_in[j], bi = b_in[j];
#pragma unroll
    for (int r = 0; r < 16; r++) {
        float p = (float)(r0 + r) - 2047.0f;
        float sg = (p > 0.f) ? 1.f : ((p < 0.f) ? -1.f : 0.f);
        float pv = sg * logf(fabsf(p) + 1.f);
        tmp[r][j] = pv * wi + bi;
    }
    __syncthreads();

    for (int layer = 0; layer < 4; layer++) {
        // LayerNorm over each row of tmp, then SiLU -> hbuf
        for (int r = warp; r < 16; r += 6) {
            float s = 0.f, s2 = 0.f;
            for (int k = lane; k < DP; k += 32) {
                float v = tmp[r][k];
                s += v; s2 += v * v;
            }
#pragma unroll
            for (int off = 16; off > 0; off >>= 1) {
                s  += __shfl_xor_sync(0xffffffffu, s,  off);
                s2 += __shfl_xor_sync(0xffffffffu, s2, off);
            }
            if (lane == 0) {
                float mu = s * (1.0f / DP);
                float var = s2 * (1.0f / DP) - mu * mu;
                mu_s[r] = mu;
                rs_s[r] = rsqrtf(var + 1e-5f);
            }
        }
        __syncthreads();
        const float gj = ln_g[layer * DP + j], bj = ln_b[layer * DP + j];
#pragma unroll
        for (int r = 0; r < 16; r++) {
            float v = (tmp[r][j] - mu_s[r]) * rs_s[r] * gj + bj;
            hbuf[r][j] = v / (1.f + expf(-v));    // SiLU
        }
        __syncthreads();

        if (layer < 3) {
            // tmp[r][j] = sum_k hbuf[r][k] * w_hid[layer][k][j] + b_hid[layer][j]
            float acc[16];
#pragma unroll
            for (int r = 0; r < 16; r++) acc[r] = 0.f;
            const float* Wp = w_hid + (size_t)layer * DP * DP + j;
            for (int k = 0; k < DP; k++) {
                float w = Wp[(size_t)k * DP];
#pragma unroll
                for (int r = 0; r < 16; r++) acc[r] = fmaf(hbuf[r][k], w, acc[r]);
            }
            const float bh = b_hid[layer * DP + j];
#pragma unroll
            for (int r = 0; r < 16; r++) tmp[r][j] = acc[r] + bh;
            __syncthreads();
        }
    }

    // output layer: 192 threads -> (row, out-channel) pairs; 16 rows x 12 ch
    const int rr = j / 12, cc = j - rr * 12;
    float a = 0.f;
    for (int k = 0; k < DP; k++) a = fmaf(hbuf[rr][k], w_out[k * 12 + cc], a);
    const int row = r0 + rr;
    if (row < NPOS) g_vals[(size_t)row * HH + cc] = a + b_out[cc];
}

// =============================================================================
// Kernel 3: flash attention with on-the-fly relative position bias.
// Grid: (N/64, B*H).  64 queries/block, 64-key tiles, 256 threads, 4x4 tiles.
// bias[h,i,j] = g_vals[(i-j+N-1)*H + h]; per tile only 127 entries -> smem.
// =============================================================================
__global__ __launch_bounds__(256) void attn_kernel()
{
    extern __shared__ float sm[];
    float* Qs     = sm;                       // [64][68] transposed: Qs[d][m]
    float* Ks     = Qs + 64 * ATT_STRIDE;     // [64][68] transposed: Ks[d][n]
    float* Vs     = Ks + 64 * ATT_STRIDE;     // [64][68] natural:    Vs[k][d]
    float* Ps     = Vs + 64 * ATT_STRIDE;     // [64][68] transposed: Ps[k][m]
    float* vals_s = Ps + 64 * ATT_STRIDE;     // [128] bias diagonal slice

    const int bh = blockIdx.y;
    const int b  = bh / HH, h = bh - b * HH;
    const int q0 = blockIdx.x * 64;
    const float* Qg = g_q + (size_t)bh * NN * DH;
    const float* Kg = g_k + (size_t)bh * NN * DH;
    const float* Vg = g_v + (size_t)bh * NN * DH;

    const int tid = threadIdx.x;
    const int tx = tid & 15, ty = tid >> 4;

    // load Q tile transposed (q already scaled by Dh^-0.5)
#pragma unroll
    for (int i = 0; i < 4; i++) {
        int idx = tid + i * 256;
        int m = idx >> 4;
        int c4 = (idx & 15) << 2;
        float4 v = *reinterpret_cast<const float4*>(&Qg[(size_t)(q0 + m) * DH + c4]);
        Qs[(c4 + 0) * ATT_STRIDE + m] = v.x;
        Qs[(c4 + 1) * ATT_STRIDE + m] = v.y;
        Qs[(c4 + 2) * ATT_STRIDE + m] = v.z;
        Qs[(c4 + 3) * ATT_STRIDE + m] = v.w;
    }

    float m_i[4], l_i[4], oacc[4][4];
#pragma unroll
    for (int i = 0; i < 4; i++) {
        m_i[i] = -1e30f;
        l_i[i] = 0.f;
#pragma unroll
        for (int j = 0; j < 4; j++) oacc[i][j] = 0.f;
    }

    for (int kt = 0; kt < NN / 64; kt++) {
        const int kk0 = kt * 64;
        // stage K (transposed), V (natural), bias slice
#pragma unroll
        for (int i = 0; i < 4; i++) {
            int idx = tid + i * 256;
            int m = idx >> 4;
            int c4 = (idx & 15) << 2;
            float4 kv = *reinterpret_cast<const float4*>(&Kg[(size_t)(kk0 + m) * DH + c4]);
            Ks[(c4 + 0) * ATT_STRIDE + m] = kv.x;
            Ks[(c4 + 1) * ATT_STRIDE + m] = kv.y;
            Ks[(c4 + 2) * ATT_STRIDE + m] = kv.z;
            Ks[(c4 + 3) * ATT_STRIDE + m] = kv.w;
            float4 vv = *reinterpret_cast<const float4*>(&Vg[(size_t)(kk0 + m) * DH + c4]);
            *reinterpret_cast<float4*>(&Vs[m * ATT_STRIDE + c4]) = vv;
        }
        {
            // needed bias indices: (q0+m)-(kk0+n)+2047, m,n in [0,64) -> 127 values
            int base = q0 - kk0 + 2047 - 63;
            if (tid < 127) vals_s[tid] = g_vals[(size_t)(base + tid) * HH + h];
        }
        __syncthreads();

        // S = Q @ K^T   (scale already folded into Q)
        float s[4][4];
#pragma unroll
        for (int i = 0; i < 4; i++)
#pragma unroll
            for (int j = 0; j < 4; j++) s[i][j] = 0.f;
#pragma unroll 8
        for (int d = 0; d < 64; d++) {
            float4 qa = *reinterpret_cast<const float4*>(&Qs[d * ATT_STRIDE + ty * 4]);
            float4 kb = *reinterpret_cast<const float4*>(&Ks[d * ATT_STRIDE + tx * 4]);
            float aa[4] = {qa.x, qa.y, qa.z, qa.w};
            float bb2[4] = {kb.x, kb.y, kb.z, kb.w};
#pragma unroll
            for (int i = 0; i < 4; i++)
#pragma unroll
                for (int j = 0; j < 4; j++)
                    s[i][j] = fmaf(aa[i], bb2[j], s[i][j]);
        }

        // + bias, online softmax update (row groups = 16 threads, shfl width 16)
#pragma unroll
        for (int i = 0; i < 4; i++) {
            int moff = ty * 4 + i - tx * 4 + 63;
#pragma unroll
            for (int j = 0; j < 4; j++) s[i][j] += vals_s[moff - j];
            float rm = fmaxf(fmaxf(s[i][0], s[i][1]), fmaxf(s[i][2], s[i][3]));
#pragma unroll
            for (int off = 8; off > 0; off >>= 1)
                rm = fmaxf(rm, __shfl_xor_sync(0xffffffffu, rm, off, 16));
            float mnew  = fmaxf(m_i[i], rm);
            float alpha = __expf(m_i[i] - mnew);
            float rsum = 0.f;
#pragma unroll
            for (int j = 0; j < 4; j++) {
                float p = __expf(s[i][j] - mnew);
                s[i][j] = p;
                rsum += p;
            }
#pragma unroll
            for (int off = 8; off > 0; off >>= 1)
                rsum += __shfl_xor_sync(0xffffffffu, rsum, off, 16);
            l_i[i] = l_i[i] * alpha + rsum;
            m_i[i] = mnew;
#pragma unroll
            for (int j = 0; j < 4; j++) oacc[i][j] *= alpha;
        }

        // write P transposed for the PV GEMM
#pragma unroll
        for (int i = 0; i < 4; i++)
#pragma unroll
            for (int j = 0; j < 4; j++)
                Ps[(tx * 4 + j) * ATT_STRIDE + ty * 4 + i] = s[i][j];
        __syncthreads();

        // O += P @ V
#pragma unroll 8
        for (int k = 0; k < 64; k++) {
            float4 pa = *reinterpret_cast<const float4*>(&Ps[k * ATT_STRIDE + ty * 4]);
            float4 vb = *reinterpret_cast<const float4*>(&Vs[k * ATT_STRIDE + tx * 4]);
            float aa[4] = {pa.x, pa.y, pa.z, pa.w};
            float bb2[4] = {vb.x, vb.y, vb.z, vb.w};
#pragma unroll
            for (int i = 0; i < 4; i++)
#pragma unroll
                for (int j = 0; j < 4; j++)
                    oacc[i][j] = fmaf(aa[i], bb2[j], oacc[i][j]);
        }
        __syncthreads();
    }

    // normalize and store to [b,n,h*64+d] for the output projection
#pragma unroll
    for (int i = 0; i < 4; i++) {
        float inv = 1.0f / l_i[i];
        float4 o;
        o.x = oacc[i][0] * inv;
        o.y = oacc[i][1] * inv;
        o.z = oacc[i][2] * inv;
        o.w = oacc[i][3] * inv;
        size_t row = (size_t)b * NN + q0 + ty * 4 + i;
        *reinterpret_cast<float4*>(&g_o[row * DD + h * DH + tx * 4]) = o;
    }
}

// =============================================================================
// Kernel 4: output projection.  g_o[4096,768] @ out_w[768,768] + out_b -> out
// =============================================================================
__global__ __launch_bounds__(256) void out_gemm(const float* __restrict__ W,
                                                const float* __restrict__ bias,
                                                float* __restrict__ out)
{
    __shared__ float As[16][ATT_STRIDE];
    __shared__ float Bs[16][ATT_STRIDE];
    const int bm = blockIdx.y * 64;
    const int bn = blockIdx.x * 64;
    const int tid = threadIdx.x;
    const int tx = tid & 15, ty = tid >> 4;
    const int ar = tid >> 2, ac = (tid & 3) << 2;
    const int br = tid >> 4, bc = (tid & 15) << 2;

    float acc[4][4] = {};
    for (int k0 = 0; k0 < 768; k0 += 16) {
        float4 a = *reinterpret_cast<const float4*>(&g_o[(size_t)(bm + ar) * 768 + k0 + ac]);
        As[ac + 0][ar] = a.x; As[ac + 1][ar] = a.y;
        As[ac + 2][ar] = a.z; As[ac + 3][ar] = a.w;
        *reinterpret_cast<float4*>(&Bs[br][bc]) =
            *reinterpret_cast<const float4*>(&W[(size_t)(k0 + br) * 768 + bn + bc]);
        __syncthreads();
#pragma unroll
        for (int kk = 0; kk < 16; kk++) {
            float4 av = *reinterpret_cast<const float4*>(&As[kk][ty * 4]);
            float4 bv = *reinterpret_cast<const float4*>(&Bs[kk][tx * 4]);
            float aa[4] = {av.x, av.y, av.z, av.w};
            float bb2[4] = {bv.x, bv.y, bv.z, bv.w};
#pragma unroll
            for (int i = 0; i < 4; i++)
#pragma unroll
                for (int j = 0; j < 4; j++)
                    acc[i][j] = fmaf(aa[i], bb2[j], acc[i][j]);
        }
        __syncthreads();
    }
    float4 bz = *reinterpret_cast<const float4*>(&bias[bn + tx * 4]);
#pragma unroll
    for (int i = 0; i < 4; i++) {
        int row = bm + ty * 4 + i;
        float4 o;
        o.x = acc[i][0] + bz.x;
        o.y = acc[i][1] + bz.y;
        o.z = acc[i][2] + bz.z;
        o.w = acc[i][3] + bz.w;
        *reinterpret_cast<float4*>(&out[(size_t)row * 768 + bn + tx * 4]) = o;
    }
}

// =============================================================================
extern "C" void kernel_launch(void* const* d_in, const int* in_sizes, int n_in,
                              void* d_out, int out_size)
{
    const float* x         = (const float*)d_in[0];
    const float* qkv_w     = (const float*)d_in[1];
    const float* qkv_b     = (const float*)d_in[2];
    const float* out_w     = (const float*)d_in[3];
    const float* out_b     = (const float*)d_in[4];
    const float* dpb_w_in  = (const float*)d_in[5];
    const float* dpb_b_in  = (const float*)d_in[6];
    const float* dpb_w_hid = (const float*)d_in[7];
    const float* dpb_b_hid = (const float*)d_in[8];
    const float* dpb_ln_g  = (const float*)d_in[9];
    const float* dpb_ln_b  = (const float*)d_in[10];
    const float* dpb_w_out = (const float*)d_in[11];
    const float* dpb_b_out = (const float*)d_in[12];
    float* out = (float*)d_out;

    const int attn_smem = (4 * 64 * ATT_STRIDE + 128) * (int)sizeof(float);  // ~70 KB
    cudaFuncSetAttribute(attn_kernel, cudaFuncAttributeMaxDynamicSharedMemorySize,
                         attn_smem);

    dpb_kernel<<<256, 192>>>(dpb_w_in, dpb_b_in, dpb_w_hid, dpb_b_hid,
                             dpb_ln_g, dpb_ln_b, dpb_w_out, dpb_b_out);
    qkv_gemm<<<dim3(36, 64), 256>>>(x, qkv_w, qkv_b);
    attn_kernel<<<dim3(32, 24), 256, attn_smem>>>();
    out_gemm<<<dim3(12, 64), 256>>>(out_w, out_b, out);
}

// round 4
// speedup vs baseline: 1.1367x; 1.1367x over previous
#include <cuda_runtime.h>

// Problem constants (fixed shapes)
#define BB   2
#define NN   2048
#define DD   768
#define HH   12
#define DH   64
#define DP   192
#define NPOS 4095   // 2*N - 1

typedef unsigned long long u64;

// ---------------- f32x2 packed-math helpers (FFMA2 path, sm_103a) -------------
__device__ __forceinline__ u64 pk2(float lo, float hi) {
    u64 r; asm("mov.b64 %0, {%1, %2};" : "=l"(r) : "f"(lo), "f"(hi)); return r;
}
__device__ __forceinline__ float2 upk2(u64 v) {
    float2 r; asm("mov.b64 {%0, %1}, %2;" : "=f"(r.x), "=f"(r.y) : "l"(v)); return r;
}
__device__ __forceinline__ void fma2(u64 &d, u64 a, u64 b) {
    asm("fma.rn.f32x2 %0, %1, %2, %0;" : "+l"(d) : "l"(a), "l"(b));
}
__device__ __forceinline__ void mul2(u64 &d, u64 a) {
    asm("mul.rn.f32x2 %0, %0, %1;" : "+l"(d) : "l"(a));
}

// ---------------- scratch (device globals; no allocations allowed) ------------
__device__ float g_q[(size_t)BB*HH*NN*DH];     // [b,h,n,d], pre-scaled by 1/8
__device__ float g_k[(size_t)BB*HH*NN*DH];
__device__ float g_v[(size_t)BB*HH*NN*DH];
__device__ float g_vals[(size_t)NPOS*HH];      // DPB MLP output [2N-1, H]
__device__ float g_o[(size_t)BB*NN*DD];        // attention output [b,n,h*64+d]

// =============================================================================
// Kernel 1: 128x128-tile SGEMM with f32x2 packed FMAs. 256 threads, 8x8/thread.
// mode 0: A = x (param),  B = qkv_w [768,2304], scatter to g_q/g_k/g_v (q*0.125)
// mode 1: A = g_o (device global — resolved INSIDE the kernel), B = out_w,
//         epilogue writes outp + bias
// =============================================================================
__global__ __launch_bounds__(256, 2) void big_gemm(const float* __restrict__ Ain,
                                                   const float* __restrict__ Bm,
                                                   int ldb, int mode,
                                                   const float* __restrict__ bias,
                                                   float* __restrict__ outp)
{
    __shared__ float As[16][132];   // transposed: As[k][m], m in [0,128)
    __shared__ float Bs[16][132];   // natural:    Bs[k][n], n in [0,128)
    const float* A = (mode == 1) ? g_o : Ain;   // device-side symbol resolution
    const int bm = blockIdx.y * 128;
    const int bn = blockIdx.x * 128;
    const int tid = threadIdx.x;
    const int tx = tid & 15, ty = tid >> 4;
    const int ar = tid >> 2, ac = (tid & 3) << 2;   // A: rows ar,+64 cols ac..+3
    const int br = tid >> 5, bc = (tid & 31) << 2;  // B: rows br,+8  cols bc..+3

    u64 acc[8][4];
#pragma unroll
    for (int i = 0; i < 8; i++)
#pragma unroll
        for (int j = 0; j < 4; j++) acc[i][j] = 0ULL;

    for (int k0 = 0; k0 < 768; k0 += 16) {
#pragma unroll
        for (int p = 0; p < 2; p++) {
            float4 a = *reinterpret_cast<const float4*>(
                &A[(size_t)(bm + ar + 64 * p) * 768 + k0 + ac]);
            As[ac + 0][ar + 64 * p] = a.x;
            As[ac + 1][ar + 64 * p] = a.y;
            As[ac + 2][ar + 64 * p] = a.z;
            As[ac + 3][ar + 64 * p] = a.w;
            *reinterpret_cast<float4*>(&Bs[br + 8 * p][bc]) =
                *reinterpret_cast<const float4*>(&Bm[(size_t)(k0 + br + 8 * p) * ldb + bn + bc]);
        }
        __syncthreads();
#pragma unroll
        for (int kk = 0; kk < 16; kk++) {
            float4 a0 = *reinterpret_cast<const float4*>(&As[kk][ty * 8]);
            float4 a1 = *reinterpret_cast<const float4*>(&As[kk][ty * 8 + 4]);
            float4 b0 = *reinterpret_cast<const float4*>(&Bs[kk][tx * 4]);
            float4 b1 = *reinterpret_cast<const float4*>(&Bs[kk][64 + tx * 4]);
            u64 bp0 = pk2(b0.x, b0.y), bp1 = pk2(b0.z, b0.w);
            u64 bp2 = pk2(b1.x, b1.y), bp3 = pk2(b1.z, b1.w);
            float av[8] = {a0.x, a0.y, a0.z, a0.w, a1.x, a1.y, a1.z, a1.w};
#pragma unroll
            for (int i = 0; i < 8; i++) {
                u64 ap = pk2(av[i], av[i]);
                fma2(acc[i][0], ap, bp0);
                fma2(acc[i][1], ap, bp1);
                fma2(acc[i][2], ap, bp2);
                fma2(acc[i][3], ap, bp3);
            }
        }
        __syncthreads();
    }

    if (mode == 0) {
#pragma unroll
        for (int g = 0; g < 2; g++) {
            const int col0 = bn + g * 64 + tx * 4;
            const int t   = col0 / 768;           // 0=q, 1=k, 2=v
            const int rem = col0 - t * 768;
            const int h   = rem >> 6;
            const int d0  = rem & 63;
            float* dst = (t == 0) ? g_q : (t == 1) ? g_k : g_v;
            const float sc = (t == 0) ? 0.125f : 1.0f;
            float4 bz = *reinterpret_cast<const float4*>(&bias[col0]);
#pragma unroll
            for (int i = 0; i < 8; i++) {
                int row = bm + ty * 8 + i;
                int b = row >> 11, n = row & 2047;
                float2 v0 = upk2(acc[i][2 * g]);
                float2 v1 = upk2(acc[i][2 * g + 1]);
                float4 o;
                o.x = (v0.x + bz.x) * sc;
                o.y = (v0.y + bz.y) * sc;
                o.z = (v1.x + bz.z) * sc;
                o.w = (v1.y + bz.w) * sc;
                *reinterpret_cast<float4*>(&dst[(((size_t)b * HH + h) * NN + n) * DH + d0]) = o;
            }
        }
    } else {
#pragma unroll
        for (int g = 0; g < 2; g++) {
            const int col0 = bn + g * 64 + tx * 4;
            float4 bz = *reinterpret_cast<const float4*>(&bias[col0]);
#pragma unroll
            for (int i = 0; i < 8; i++) {
                int row = bm + ty * 8 + i;
                float2 v0 = upk2(acc[i][2 * g]);
                float2 v1 = upk2(acc[i][2 * g + 1]);
                float4 o;
                o.x = v0.x + bz.x;
                o.y = v0.y + bz.y;
                o.z = v1.x + bz.z;
                o.w = v1.y + bz.w;
                *reinterpret_cast<float4*>(&outp[(size_t)row * 768 + col0]) = o;
            }
        }
    }
}

// =============================================================================
// Kernel 2: DynamicPositionBias MLP, fully fused.  16 rows per block, 192 thr.
// =============================================================================
__global__ __launch_bounds__(192) void dpb_kernel(const float* __restrict__ w_in,
                                                  const float* __restrict__ b_in,
                                                  const float* __restrict__ w_hid,
                                                  const float* __restrict__ b_hid,
                                                  const float* __restrict__ ln_g,
                                                  const float* __restrict__ ln_b,
                                                  const float* __restrict__ w_out,
                                                  const float* __restrict__ b_out)
{
    __shared__ float hbuf[16][DP];
    __shared__ float tmp[16][DP];
    __shared__ float mu_s[16], rs_s[16];
    const int j    = threadIdx.x;         // 0..191
    const int r0   = blockIdx.x * 16;
    const int warp = j >> 5, lane = j & 31;

    const float wi = w_in[j], bi = b_in[j];
#pragma unroll
    for (int r = 0; r < 16; r++) {
        float p = (float)(r0 + r) - 2047.0f;
        float sg = (p > 0.f) ? 1.f : ((p < 0.f) ? -1.f : 0.f);
        float pv = sg * logf(fabsf(p) + 1.f);
        tmp[r][j] = pv * wi + bi;
    }
    __syncthreads();

    for (int layer = 0; layer < 4; layer++) {
        for (int r = warp; r < 16; r += 6) {
            float s = 0.f, s2 = 0.f;
            for (int k = lane; k < DP; k += 32) {
                float v = tmp[r][k];
                s += v; s2 += v * v;
            }
#pragma unroll
            for (int off = 16; off > 0; off >>= 1) {
                s  += __shfl_xor_sync(0xffffffffu, s,  off);
                s2 += __shfl_xor_sync(0xffffffffu, s2, off);
            }
            if (lane == 0) {
                float mu = s * (1.0f / DP);
                float var = s2 * (1.0f / DP) - mu * mu;
                mu_s[r] = mu;
                rs_s[r] = rsqrtf(var + 1e-5f);
            }
        }
        __syncthreads();
        const float gj = ln_g[layer * DP + j], bj = ln_b[layer * DP + j];
#pragma unroll
        for (int r = 0; r < 16; r++) {
            float v = (tmp[r][j] - mu_s[r]) * rs_s[r] * gj + bj;
            hbuf[r][j] = v / (1.f + expf(-v));    // SiLU
        }
        __syncthreads();

        if (layer < 3) {
            float acc[16];
#pragma unroll
            for (int r = 0; r < 16; r++) acc[r] = 0.f;
            const float* Wp = w_hid + (size_t)layer * DP * DP + j;
            for (int k = 0; k < DP; k++) {
                float w = Wp[(size_t)k * DP];
#pragma unroll
                for (int r = 0; r < 16; r++) acc[r] = fmaf(hbuf[r][k], w, acc[r]);
            }
            const float bh = b_hid[layer * DP + j];
#pragma unroll
            for (int r = 0; r < 16; r++) tmp[r][j] = acc[r] + bh;
            __syncthreads();
        }
    }

    const int rr = j / 12, cc = j - rr * 12;
    float a = 0.f;
    for (int k = 0; k < DP; k++) a = fmaf(hbuf[rr][k], w_out[k * 12 + cc], a);
    const int row = r0 + rr;
    if (row < NPOS) g_vals[(size_t)row * HH + cc] = a + b_out[cc];
}

// =============================================================================
// Kernel 3: flash attention, 128 queries x 64 keys per tile, 256 threads,
// 8x4 per thread, f32x2 packed FMAs in both QK^T and PV loops.
// bias[h,i,j] = g_vals[(i-j+N-1)*H + h]; per tile only 191 entries -> smem.
// =============================================================================
#define QS 132   // stride for 128-wide transposed tiles (Qs, Ps)
#define KS 68    // stride for 64-wide tiles (Ks, Vs)

__global__ __launch_bounds__(256, 1) void attn_kernel()
{
    extern __shared__ float sm[];
    float* Qs     = sm;                    // [64][132] transposed: Qs[d][m]
    float* Ks     = Qs + 64 * QS;          // [64][68]  transposed: Ks[d][n]
    float* Vs     = Ks + 64 * KS;          // [64][68]  natural:    Vs[k][d]
    float* Ps     = Vs + 64 * KS;          // [64][132] transposed: Ps[k][m]
    float* vals_s = Ps + 64 * QS;          // [192] bias diagonal slice

    const int bh = blockIdx.y;
    const int b  = bh / HH, h = bh - b * HH;
    const int q0 = blockIdx.x * 128;
    const float* Qg = g_q + (size_t)bh * NN * DH;
    const float* Kg = g_k + (size_t)bh * NN * DH;
    const float* Vg = g_v + (size_t)bh * NN * DH;

    const int tid = threadIdx.x;
    const int tx = tid & 15, ty = tid >> 4;

    // load Q tile (128x64) transposed; q already scaled by Dh^-0.5
#pragma unroll
    for (int i = 0; i < 8; i++) {
        int idx = tid + i * 256;
        int m = idx >> 4;
        int c4 = (idx & 15) << 2;
        float4 v = *reinterpret_cast<const float4*>(&Qg[(size_t)(q0 + m) * DH + c4]);
        Qs[(c4 + 0) * QS + m] = v.x;
        Qs[(c4 + 1) * QS + m] = v.y;
        Qs[(c4 + 2) * QS + m] = v.z;
        Qs[(c4 + 3) * QS + m] = v.w;
    }

    float m_i[8], l_i[8];
    u64 oacc[8][2];
#pragma unroll
    for (int i = 0; i < 8; i++) {
        m_i[i] = -1e30f;
        l_i[i] = 0.f;
        oacc[i][0] = 0ULL;
        oacc[i][1] = 0ULL;
    }

    for (int kt = 0; kt < NN / 64; kt++) {
        const int kk0 = kt * 64;
        // stage K (transposed), V (natural), bias slice
#pragma unroll
        for (int i = 0; i < 4; i++) {
            int idx = tid + i * 256;
            int m = idx >> 4;
            int c4 = (idx & 15) << 2;
            float4 kv = *reinterpret_cast<const float4*>(&Kg[(size_t)(kk0 + m) * DH + c4]);
            Ks[(c4 + 0) * KS + m] = kv.x;
            Ks[(c4 + 1) * KS + m] = kv.y;
            Ks[(c4 + 2) * KS + m] = kv.z;
            Ks[(c4 + 3) * KS + m] = kv.w;
            float4 vv = *reinterpret_cast<const float4*>(&Vg[(size_t)(kk0 + m) * DH + c4]);
            *reinterpret_cast<float4*>(&Vs[m * KS + c4]) = vv;
        }
        {
            // needed bias indices: (q0+m)-(kk0+n)+2047 -> 191 values
            int base = q0 - kk0 + 2047 - 63;
            if (tid < 191) vals_s[tid] = g_vals[(size_t)(base + tid) * HH + h];
        }
        __syncthreads();

        // S = Q @ K^T  (128x64), packed f32x2 accumulation
        u64 sacc[8][2];
#pragma unroll
        for (int i = 0; i < 8; i++) { sacc[i][0] = 0ULL; sacc[i][1] = 0ULL; }
#pragma unroll 4
        for (int d = 0; d < 64; d++) {
            float4 qa = *reinterpret_cast<const float4*>(&Qs[d * QS + ty * 8]);
            float4 qb = *reinterpret_cast<const float4*>(&Qs[d * QS + ty * 8 + 4]);
            float4 kb = *reinterpret_cast<const float4*>(&Ks[d * KS + tx * 4]);
            u64 bp0 = pk2(kb.x, kb.y), bp1 = pk2(kb.z, kb.w);
            float av[8] = {qa.x, qa.y, qa.z, qa.w, qb.x, qb.y, qb.z, qb.w};
#pragma unroll
            for (int i = 0; i < 8; i++) {
                u64 ap = pk2(av[i], av[i]);
                fma2(sacc[i][0], ap, bp0);
                fma2(sacc[i][1], ap, bp1);
            }
        }

        // + bias, online softmax (rows share 16 threads; shfl width 16)
#pragma unroll
        for (int i = 0; i < 8; i++) {
            float2 p0 = upk2(sacc[i][0]);
            float2 p1 = upk2(sacc[i][1]);
            float s0 = p0.x, s1 = p0.y, s2 = p1.x, s3 = p1.y;
            int moff = ty * 8 + i - tx * 4 + 63;
            s0 += vals_s[moff];
            s1 += vals_s[moff - 1];
            s2 += vals_s[moff - 2];
            s3 += vals_s[moff - 3];
            float rm = fmaxf(fmaxf(s0, s1), fmaxf(s2, s3));
#pragma unroll
            for (int off = 8; off > 0; off >>= 1)
                rm = fmaxf(rm, __shfl_xor_sync(0xffffffffu, rm, off, 16));
            float mnew  = fmaxf(m_i[i], rm);
            float alpha = __expf(m_i[i] - mnew);
            s0 = __expf(s0 - mnew);
            s1 = __expf(s1 - mnew);
            s2 = __expf(s2 - mnew);
            s3 = __expf(s3 - mnew);
            float rsum = s0 + s1 + s2 + s3;
#pragma unroll
            for (int off = 8; off > 0; off >>= 1)
                rsum += __shfl_xor_sync(0xffffffffu, rsum, off, 16);
            l_i[i] = l_i[i] * alpha + rsum;
            m_i[i] = mnew;
            u64 alp = pk2(alpha, alpha);
            mul2(oacc[i][0], alp);
            mul2(oacc[i][1], alp);
            // write P transposed for the PV GEMM
            Ps[(tx * 4 + 0) * QS + ty * 8 + i] = s0;
            Ps[(tx * 4 + 1) * QS + ty * 8 + i] = s1;
            Ps[(tx * 4 + 2) * QS + ty * 8 + i] = s2;
            Ps[(tx * 4 + 3) * QS + ty * 8 + i] = s3;
        }
        __syncthreads();

        // O += P @ V  (128x64 += 128x64 @ 64x64), packed f32x2
#pragma unroll 4
        for (int k = 0; k < 64; k++) {
            float4 pa = *reinterpret_cast<const float4*>(&Ps[k * QS + ty * 8]);
            float4 pb = *reinterpret_cast<const float4*>(&Ps[k * QS + ty * 8 + 4]);
            float4 vb = *reinterpret_cast<const float4*>(&Vs[k * KS + tx * 4]);
            u64 bp0 = pk2(vb.x, vb.y), bp1 = pk2(vb.z, vb.w);
            float av[8] = {pa.x, pa.y, pa.z, pa.w, pb.x, pb.y, pb.z, pb.w};
#pragma unroll
            for (int i = 0; i < 8; i++) {
                u64 ap = pk2(av[i], av[i]);
                fma2(oacc[i][0], ap, bp0);
                fma2(oacc[i][1], ap, bp1);
            }
        }
        __syncthreads();
    }

    // normalize and store to [b,n,h*64+d] for the output projection
#pragma unroll
    for (int i = 0; i < 8; i++) {
        float inv = 1.0f / l_i[i];
        float2 v0 = upk2(oacc[i][0]);
        float2 v1 = upk2(oacc[i][1]);
        float4 o;
        o.x = v0.x * inv;
        o.y = v0.y * inv;
        o.z = v1.x * inv;
        o.w = v1.y * inv;
        size_t row = (size_t)b * NN + q0 + ty * 8 + i;
        *reinterpret_cast<float4*>(&g_o[row * DD + h * DH + tx * 4]) = o;
    }
}

// =============================================================================
extern "C" void kernel_launch(void* const* d_in, const int* in_sizes, int n_in,
                              void* d_out, int out_size)
{
    const float* x         = (const float*)d_in[0];
    const float* qkv_w     = (const float*)d_in[1];
    const float* qkv_b     = (const float*)d_in[2];
    const float* out_w     = (const float*)d_in[3];
    const float* out_b     = (const float*)d_in[4];
    const float* dpb_w_in  = (const float*)d_in[5];
    const float* dpb_b_in  = (const float*)d_in[6];
    const float* dpb_w_hid = (const float*)d_in[7];
    const float* dpb_b_hid = (const float*)d_in[8];
    const float* dpb_ln_g  = (const float*)d_in[9];
    const float* dpb_ln_b  = (const float*)d_in[10];
    const float* dpb_w_out = (const float*)d_in[11];
    const float* dpb_b_out = (const float*)d_in[12];
    float* out = (float*)d_out;

    const int attn_smem = (64 * QS + 64 * KS + 64 * KS + 64 * QS + 192) * (int)sizeof(float);
    cudaFuncSetAttribute(attn_kernel, cudaFuncAttributeMaxDynamicSharedMemorySize,
                         attn_smem);

    dpb_kernel<<<256, 192>>>(dpb_w_in, dpb_b_in, dpb_w_hid, dpb_b_hid,
                             dpb_ln_g, dpb_ln_b, dpb_w_out, dpb_b_out);
    big_gemm<<<dim3(18, 32), 256>>>(x, qkv_w, 2304, 0, qkv_b, nullptr);
    attn_kernel<<<dim3(16, 24), 256, attn_smem>>>();
    big_gemm<<<dim3(6, 32), 256>>>(nullptr, out_w, 768, 1, out_b, out);
}

// round 5
// speedup vs baseline: 1.1390x; 1.0020x over previous
#include <cuda_runtime.h>

// Problem constants (fixed shapes)
#define BB   2
#define NN   2048
#define DD   768
#define HH   12
#define DH   64
#define DP   192
#define NPOS 4095   // 2*N - 1

typedef unsigned long long u64;

// ---------------- f32x2 packed-math helpers (FFMA2 path, sm_103a) -------------
__device__ __forceinline__ u64 pk2(float lo, float hi) {
    u64 r; asm("mov.b64 %0, {%1, %2};" : "=l"(r) : "f"(lo), "f"(hi)); return r;
}
__device__ __forceinline__ float2 upk2(u64 v) {
    float2 r; asm("mov.b64 {%0, %1}, %2;" : "=f"(r.x), "=f"(r.y) : "l"(v)); return r;
}
__device__ __forceinline__ void fma2(u64 &d, u64 a, u64 b) {
    asm("fma.rn.f32x2 %0, %1, %2, %0;" : "+l"(d) : "l"(a), "l"(b));
}
__device__ __forceinline__ void mul2(u64 &d, u64 a) {
    asm("mul.rn.f32x2 %0, %0, %1;" : "+l"(d) : "l"(a));
}

// ---------------- scratch (device globals; no allocations allowed) ------------
__device__ float g_q[(size_t)BB*HH*NN*DH];     // [b,h,n,d], pre-scaled by 1/8
__device__ float g_k[(size_t)BB*HH*NN*DH];
__device__ float g_v[(size_t)BB*HH*NN*DH];
__device__ float g_vals[(size_t)NPOS*HH];      // DPB MLP output [2N-1, H]
__device__ float g_o[(size_t)BB*NN*DD];        // attention output [b,n,h*64+d]

// =============================================================================
// Kernel 1: 128x128-tile SGEMM with f32x2 packed FMAs. 256 threads, 8x8/thread.
// mode 0: A = x (param),  B = qkv_w [768,2304], scatter to g_q/g_k/g_v (q*0.125)
// mode 1: A = g_o (device global — resolved INSIDE the kernel), B = out_w,
//         epilogue writes outp + bias
// =============================================================================
__global__ __launch_bounds__(256, 2) void big_gemm(const float* __restrict__ Ain,
                                                   const float* __restrict__ Bm,
                                                   int ldb, int mode,
                                                   const float* __restrict__ bias,
                                                   float* __restrict__ outp)
{
    __shared__ float As[16][132];   // transposed: As[k][m], m in [0,128)
    __shared__ float Bs[16][132];   // natural:    Bs[k][n], n in [0,128)
    const float* A = (mode == 1) ? g_o : Ain;   // device-side symbol resolution
    const int bm = blockIdx.y * 128;
    const int bn = blockIdx.x * 128;
    const int tid = threadIdx.x;
    const int tx = tid & 15, ty = tid >> 4;
    const int ar = tid >> 2, ac = (tid & 3) << 2;   // A: rows ar,+64 cols ac..+3
    const int br = tid >> 5, bc = (tid & 31) << 2;  // B: rows br,+8  cols bc..+3

    u64 acc[8][4];
#pragma unroll
    for (int i = 0; i < 8; i++)
#pragma unroll
        for (int j = 0; j < 4; j++) acc[i][j] = 0ULL;

    for (int k0 = 0; k0 < 768; k0 += 16) {
#pragma unroll
        for (int p = 0; p < 2; p++) {
            float4 a = *reinterpret_cast<const float4*>(
                &A[(size_t)(bm + ar + 64 * p) * 768 + k0 + ac]);
            As[ac + 0][ar + 64 * p] = a.x;
            As[ac + 1][ar + 64 * p] = a.y;
            As[ac + 2][ar + 64 * p] = a.z;
            As[ac + 3][ar + 64 * p] = a.w;
            *reinterpret_cast<float4*>(&Bs[br + 8 * p][bc]) =
                *reinterpret_cast<const float4*>(&Bm[(size_t)(k0 + br + 8 * p) * ldb + bn + bc]);
        }
        __syncthreads();
#pragma unroll
        for (int kk = 0; kk < 16; kk++) {
            float4 a0 = *reinterpret_cast<const float4*>(&As[kk][ty * 8]);
            float4 a1 = *reinterpret_cast<const float4*>(&As[kk][ty * 8 + 4]);
            float4 b0 = *reinterpret_cast<const float4*>(&Bs[kk][tx * 4]);
            float4 b1 = *reinterpret_cast<const float4*>(&Bs[kk][64 + tx * 4]);
            u64 bp0 = pk2(b0.x, b0.y), bp1 = pk2(b0.z, b0.w);
            u64 bp2 = pk2(b1.x, b1.y), bp3 = pk2(b1.z, b1.w);
            float av[8] = {a0.x, a0.y, a0.z, a0.w, a1.x, a1.y, a1.z, a1.w};
#pragma unroll
            for (int i = 0; i < 8; i++) {
                u64 ap = pk2(av[i], av[i]);
                fma2(acc[i][0], ap, bp0);
                fma2(acc[i][1], ap, bp1);
                fma2(acc[i][2], ap, bp2);
                fma2(acc[i][3], ap, bp3);
            }
        }
        __syncthreads();
    }

    if (mode == 0) {
#pragma unroll
        for (int g = 0; g < 2; g++) {
            const int col0 = bn + g * 64 + tx * 4;
            const int t   = col0 / 768;           // 0=q, 1=k, 2=v
            const int rem = col0 - t * 768;
            const int h   = rem >> 6;
            const int d0  = rem & 63;
            float* dst = (t == 0) ? g_q : (t == 1) ? g_k : g_v;
            const float sc = (t == 0) ? 0.125f : 1.0f;
            float4 bz = *reinterpret_cast<const float4*>(&bias[col0]);
#pragma unroll
            for (int i = 0; i < 8; i++) {
                int row = bm + ty * 8 + i;
                int b = row >> 11, n = row & 2047;
                float2 v0 = upk2(acc[i][2 * g]);
                float2 v1 = upk2(acc[i][2 * g + 1]);
                float4 o;
                o.x = (v0.x + bz.x) * sc;
                o.y = (v0.y + bz.y) * sc;
                o.z = (v1.x + bz.z) * sc;
                o.w = (v1.y + bz.w) * sc;
                *reinterpret_cast<float4*>(&dst[(((size_t)b * HH + h) * NN + n) * DH + d0]) = o;
            }
        }
    } else {
#pragma unroll
        for (int g = 0; g < 2; g++) {
            const int col0 = bn + g * 64 + tx * 4;
            float4 bz = *reinterpret_cast<const float4*>(&bias[col0]);
#pragma unroll
            for (int i = 0; i < 8; i++) {
                int row = bm + ty * 8 + i;
                float2 v0 = upk2(acc[i][2 * g]);
                float2 v1 = upk2(acc[i][2 * g + 1]);
                float4 o;
                o.x = v0.x + bz.x;
                o.y = v0.y + bz.y;
                o.z = v1.x + bz.z;
                o.w = v1.y + bz.w;
                *reinterpret_cast<float4*>(&outp[(size_t)row * 768 + col0]) = o;
            }
        }
    }
}

// =============================================================================
// Kernel 2: DynamicPositionBias MLP, fully fused.  16 rows per block, 192 thr.
// =============================================================================
__global__ __launch_bounds__(192) void dpb_kernel(const float* __restrict__ w_in,
                                                  const float* __restrict__ b_in,
                                                  const float* __restrict__ w_hid,
                                                  const float* __restrict__ b_hid,
                                                  const float* __restrict__ ln_g,
                                                  const float* __restrict__ ln_b,
                                                  const float* __restrict__ w_out,
                                                  const float* __restrict__ b_out)
{
    __shared__ float hbuf[16][DP];
    __shared__ float tmp[16][DP];
    __shared__ float mu_s[16], rs_s[16];
    const int j    = threadIdx.x;         // 0..191
    const int r0   = blockIdx.x * 16;
    const int warp = j >> 5, lane = j & 31;

    const float wi = w_in[j], bi = b_in[j];
#pragma unroll
    for (int r = 0; r < 16; r++) {
        float p = (float)(r0 + r) - 2047.0f;
        float sg = (p > 0.f) ? 1.f : ((p < 0.f) ? -1.f : 0.f);
        float pv = sg * logf(fabsf(p) + 1.f);
        tmp[r][j] = pv * wi + bi;
    }
    __syncthreads();

    for (int layer = 0; layer < 4; layer++) {
        for (int r = warp; r < 16; r += 6) {
            float s = 0.f, s2 = 0.f;
            for (int k = lane; k < DP; k += 32) {
                float v = tmp[r][k];
                s += v; s2 += v * v;
            }
#pragma unroll
            for (int off = 16; off > 0; off >>= 1) {
                s  += __shfl_xor_sync(0xffffffffu, s,  off);
                s2 += __shfl_xor_sync(0xffffffffu, s2, off);
            }
            if (lane == 0) {
                float mu = s * (1.0f / DP);
                float var = s2 * (1.0f / DP) - mu * mu;
                mu_s[r] = mu;
                rs_s[r] = rsqrtf(var + 1e-5f);
            }
        }
        __syncthreads();
        const float gj = ln_g[layer * DP + j], bj = ln_b[layer * DP + j];
#pragma unroll
        for (int r = 0; r < 16; r++) {
            float v = (tmp[r][j] - mu_s[r]) * rs_s[r] * gj + bj;
            hbuf[r][j] = v / (1.f + expf(-v));    // SiLU
        }
        __syncthreads();

        if (layer < 3) {
            float acc[16];
#pragma unroll
            for (int r = 0; r < 16; r++) acc[r] = 0.f;
            const float* Wp = w_hid + (size_t)layer * DP * DP + j;
            for (int k = 0; k < DP; k++) {
                float w = Wp[(size_t)k * DP];
#pragma unroll
                for (int r = 0; r < 16; r++) acc[r] = fmaf(hbuf[r][k], w, acc[r]);
            }
            const float bh = b_hid[layer * DP + j];
#pragma unroll
            for (int r = 0; r < 16; r++) tmp[r][j] = acc[r] + bh;
            __syncthreads();
        }
    }

    const int rr = j / 12, cc = j - rr * 12;
    float a = 0.f;
    for (int k = 0; k < DP; k++) a = fmaf(hbuf[rr][k], w_out[k * 12 + cc], a);
    const int row = r0 + rr;
    if (row < NPOS) g_vals[(size_t)row * HH + cc] = a + b_out[cc];
}

// =============================================================================
// Kernel 3: flash attention, 128 queries x 64 keys per tile, 256 threads,
// 8x4 per thread, f32x2 packed FMAs in both QK^T and PV loops.
// bias[h,i,j] = g_vals[(i-j+N-1)*H + h]; per tile only 191 entries -> smem.
// =============================================================================
#define QS 132   // stride for 128-wide transposed tiles (Qs, Ps)
#define KS 68    // stride for 64-wide tiles (Ks, Vs)

__global__ __launch_bounds__(256, 1) void attn_kernel()
{
    extern __shared__ float sm[];
    float* Qs     = sm;                    // [64][132] transposed: Qs[d][m]
    float* Ks     = Qs + 64 * QS;          // [64][68]  transposed: Ks[d][n]
    float* Vs     = Ks + 64 * KS;          // [64][68]  natural:    Vs[k][d]
    float* Ps     = Vs + 64 * KS;          // [64][132] transposed: Ps[k][m]
    float* vals_s = Ps + 64 * QS;          // [192] bias diagonal slice

    const int bh = blockIdx.y;
    const int b  = bh / HH, h = bh - b * HH;
    const int q0 = blockIdx.x * 128;
    const float* Qg = g_q + (size_t)bh * NN * DH;
    const float* Kg = g_k + (size_t)bh * NN * DH;
    const float* Vg = g_v + (size_t)bh * NN * DH;

    const int tid = threadIdx.x;
    const int tx = tid & 15, ty = tid >> 4;

    // load Q tile (128x64) transposed; q already scaled by Dh^-0.5
#pragma unroll
    for (int i = 0; i < 8; i++) {
        int idx = tid + i * 256;
        int m = idx >> 4;
        int c4 = (idx & 15) << 2;
        float4 v = *reinterpret_cast<const float4*>(&Qg[(size_t)(q0 + m) * DH + c4]);
        Qs[(c4 + 0) * QS + m] = v.x;
        Qs[(c4 + 1) * QS + m] = v.y;
        Qs[(c4 + 2) * QS + m] = v.z;
        Qs[(c4 + 3) * QS + m] = v.w;
    }

    float m_i[8], l_i[8];
    u64 oacc[8][2];
#pragma unroll
    for (int i = 0; i < 8; i++) {
        m_i[i] = -1e30f;
        l_i[i] = 0.f;
        oacc[i][0] = 0ULL;
        oacc[i][1] = 0ULL;
    }

    for (int kt = 0; kt < NN / 64; kt++) {
        const int kk0 = kt * 64;
        // stage K (transposed), V (natural), bias slice
#pragma unroll
        for (int i = 0; i < 4; i++) {
            int idx = tid + i * 256;
            int m = idx >> 4;
            int c4 = (idx & 15) << 2;
            float4 kv = *reinterpret_cast<const float4*>(&Kg[(size_t)(kk0 + m) * DH + c4]);
            Ks[(c4 + 0) * KS + m] = kv.x;
            Ks[(c4 + 1) * KS + m] = kv.y;
            Ks[(c4 + 2) * KS + m] = kv.z;
            Ks[(c4 + 3) * KS + m] = kv.w;
            float4 vv = *reinterpret_cast<const float4*>(&Vg[(size_t)(kk0 + m) * DH + c4]);
            *reinterpret_cast<float4*>(&Vs[m * KS + c4]) = vv;
        }
        {
            // needed bias indices: (q0+m)-(kk0+n)+2047 -> 191 values
            int base = q0 - kk0 + 2047 - 63;
            if (tid < 191) vals_s[tid] = g_vals[(size_t)(base + tid) * HH + h];
        }
        __syncthreads();

        // S = Q @ K^T  (128x64), packed f32x2 accumulation
        u64 sacc[8][2];
#pragma unroll
        for (int i = 0; i < 8; i++) { sacc[i][0] = 0ULL; sacc[i][1] = 0ULL; }
#pragma unroll 4
        for (int d = 0; d < 64; d++) {
            float4 qa = *reinterpret_cast<const float4*>(&Qs[d * QS + ty * 8]);
            float4 qb = *reinterpret_cast<const float4*>(&Qs[d * QS + ty * 8 + 4]);
            float4 kb = *reinterpret_cast<const float4*>(&Ks[d * KS + tx * 4]);
            u64 bp0 = pk2(kb.x, kb.y), bp1 = pk2(kb.z, kb.w);
            float av[8] = {qa.x, qa.y, qa.z, qa.w, qb.x, qb.y, qb.z, qb.w};
#pragma unroll
            for (int i = 0; i < 8; i++) {
                u64 ap = pk2(av[i], av[i]);
                fma2(sacc[i][0], ap, bp0);
                fma2(sacc[i][1], ap, bp1);
            }
        }

        // + bias, online softmax (rows share 16 threads; shfl width 16)
#pragma unroll
        for (int i = 0; i < 8; i++) {
            float2 p0 = upk2(sacc[i][0]);
            float2 p1 = upk2(sacc[i][1]);
            float s0 = p0.x, s1 = p0.y, s2 = p1.x, s3 = p1.y;
            int moff = ty * 8 + i - tx * 4 + 63;
            s0 += vals_s[moff];
            s1 += vals_s[moff - 1];
            s2 += vals_s[moff - 2];
            s3 += vals_s[moff - 3];
            float rm = fmaxf(fmaxf(s0, s1), fmaxf(s2, s3));
#pragma unroll
            for (int off = 8; off > 0; off >>= 1)
                rm = fmaxf(rm, __shfl_xor_sync(0xffffffffu, rm, off, 16));
            float mnew  = fmaxf(m_i[i], rm);
            float alpha = __expf(m_i[i] - mnew);
            s0 = __expf(s0 - mnew);
            s1 = __expf(s1 - mnew);
            s2 = __expf(s2 - mnew);
            s3 = __expf(s3 - mnew);
            float rsum = s0 + s1 + s2 + s3;
#pragma unroll
            for (int off = 8; off > 0; off >>= 1)
                rsum += __shfl_xor_sync(0xffffffffu, rsum, off, 16);
            l_i[i] = l_i[i] * alpha + rsum;
            m_i[i] = mnew;
            u64 alp = pk2(alpha, alpha);
            mul2(oacc[i][0], alp);
            mul2(oacc[i][1], alp);
            // write P transposed for the PV GEMM
            Ps[(tx * 4 + 0) * QS + ty * 8 + i] = s0;
            Ps[(tx * 4 + 1) * QS + ty * 8 + i] = s1;
            Ps[(tx * 4 + 2) * QS + ty * 8 + i] = s2;
            Ps[(tx * 4 + 3) * QS + ty * 8 + i] = s3;
        }
        __syncthreads();

        // O += P @ V  (128x64 += 128x64 @ 64x64), packed f32x2
#pragma unroll 4
        for (int k = 0; k < 64; k++) {
            float4 pa = *reinterpret_cast<const float4*>(&Ps[k * QS + ty * 8]);
            float4 pb = *reinterpret_cast<const float4*>(&Ps[k * QS + ty * 8 + 4]);
            float4 vb = *reinterpret_cast<const float4*>(&Vs[k * KS + tx * 4]);
            u64 bp0 = pk2(vb.x, vb.y), bp1 = pk2(vb.z, vb.w);
            float av[8] = {pa.x, pa.y, pa.z, pa.w, pb.x, pb.y, pb.z, pb.w};
#pragma unroll
            for (int i = 0; i < 8; i++) {
                u64 ap = pk2(av[i], av[i]);
                fma2(oacc[i][0], ap, bp0);
                fma2(oacc[i][1], ap, bp1);
            }
        }
        __syncthreads();
    }

    // normalize and store to [b,n,h*64+d] for the output projection
#pragma unroll
    for (int i = 0; i < 8; i++) {
        float inv = 1.0f / l_i[i];
        float2 v0 = upk2(oacc[i][0]);
        float2 v1 = upk2(oacc[i][1]);
        float4 o;
        o.x = v0.x * inv;
        o.y = v0.y * inv;
        o.z = v1.x * inv;
        o.w = v1.y * inv;
        size_t row = (size_t)b * NN + q0 + ty * 8 + i;
        *reinterpret_cast<float4*>(&g_o[row * DD + h * DH + tx * 4]) = o;
    }
}

// =============================================================================
extern "C" void kernel_launch(void* const* d_in, const int* in_sizes, int n_in,
                              void* d_out, int out_size)
{
    const float* x         = (const float*)d_in[0];
    const float* qkv_w     = (const float*)d_in[1];
    const float* qkv_b     = (const float*)d_in[2];
    const float* out_w     = (const float*)d_in[3];
    const float* out_b     = (const float*)d_in[4];
    const float* dpb_w_in  = (const float*)d_in[5];
    const float* dpb_b_in  = (const float*)d_in[6];
    const float* dpb_w_hid = (const float*)d_in[7];
    const float* dpb_b_hid = (const float*)d_in[8];
    const float* dpb_ln_g  = (const float*)d_in[9];
    const float* dpb_ln_b  = (const float*)d_in[10];
    const float* dpb_w_out = (const float*)d_in[11];
    const float* dpb_b_out = (const float*)d_in[12];
    float* out = (float*)d_out;

    const int attn_smem = (64 * QS + 64 * KS + 64 * KS + 64 * QS + 192) * (int)sizeof(float);
    cudaFuncSetAttribute(attn_kernel, cudaFuncAttributeMaxDynamicSharedMemorySize,
                         attn_smem);

    dpb_kernel<<<256, 192>>>(dpb_w_in, dpb_b_in, dpb_w_hid, dpb_b_hid,
                             dpb_ln_g, dpb_ln_b, dpb_w_out, dpb_b_out);
    big_gemm<<<dim3(18, 32), 256>>>(x, qkv_w, 2304, 0, qkv_b, nullptr);
    attn_kernel<<<dim3(16, 24), 256, attn_smem>>>();
    big_gemm<<<dim3(6, 32), 256>>>(nullptr, out_w, 768, 1, out_b, out);
}

// round 6
// speedup vs baseline: 1.1671x; 1.0246x over previous
#include <cuda_runtime.h>

// Problem constants (fixed shapes)
#define BB   2
#define NN   2048
#define DD   768
#define HH   12
#define DH   64
#define DP   192
#define NPOS 4095   // 2*N - 1

typedef unsigned long long u64;

// ---------------- f32x2 packed-math helpers (FFMA2 path, sm_103a) -------------
__device__ __forceinline__ u64 pk2(float lo, float hi) {
    u64 r; asm("mov.b64 %0, {%1, %2};" : "=l"(r) : "f"(lo), "f"(hi)); return r;
}
__device__ __forceinline__ float2 upk2(u64 v) {
    float2 r; asm("mov.b64 {%0, %1}, %2;" : "=f"(r.x), "=f"(r.y) : "l"(v)); return r;
}
__device__ __forceinline__ void fma2(u64 &d, u64 a, u64 b) {
    asm("fma.rn.f32x2 %0, %1, %2, %0;" : "+l"(d) : "l"(a), "l"(b));
}
__device__ __forceinline__ void mul2(u64 &d, u64 a) {
    asm("mul.rn.f32x2 %0, %0, %1;" : "+l"(d) : "l"(a));
}

// ---------------- cp.async helpers (LDGSTS) -----------------------------------
__device__ __forceinline__ void cpa16(void* smem_dst, const void* gmem_src) {
    unsigned s = (unsigned)__cvta_generic_to_shared(smem_dst);
    asm volatile("cp.async.cg.shared.global [%0], [%1], 16;" :: "r"(s), "l"(gmem_src));
}
__device__ __forceinline__ void cpa_commit() {
    asm volatile("cp.async.commit_group;");
}
__device__ __forceinline__ void cpa_wait0() {
    asm volatile("cp.async.wait_group 0;");
}

// ---------------- scratch (device globals; no allocations allowed) ------------
__device__ float g_q[(size_t)BB*HH*NN*DH];     // [b,h,n,d], pre-scaled by 1/8
__device__ float g_k[(size_t)BB*HH*NN*DH];
__device__ float g_v[(size_t)BB*HH*NN*DH];
__device__ float g_vals[(size_t)NPOS*HH];      // DPB MLP output [2N-1, H]
__device__ float g_o[(size_t)BB*NN*DD];        // attention output [b,n,h*64+d]

// =============================================================================
// Kernel 1: 128x128-tile SGEMM, f32x2 FMAs, double-buffered smem.
// B tiles arrive via cp.async (no transpose needed); A tiles prefetched via
// registers (transposed on store).  256 threads, 8x8/thread.
// mode 0: A = x,  B = qkv_w [768,2304], scatter to g_q/g_k/g_v (q*0.125)
// mode 1: A = g_o (device symbol resolved in-kernel), B = out_w, write outp.
// =============================================================================
__global__ __launch_bounds__(256, 2) void big_gemm(const float* __restrict__ Ain,
                                                   const float* __restrict__ Bm,
                                                   int ldb, int mode,
                                                   const float* __restrict__ bias,
                                                   float* __restrict__ outp)
{
    __shared__ float As[2][16][132];   // transposed: As[buf][k][m]
    __shared__ float Bs[2][16][132];   // natural:    Bs[buf][k][n]
    const float* A = (mode == 1) ? g_o : Ain;
    const int bm = blockIdx.y * 128;
    const int bn = blockIdx.x * 128;
    const int tid = threadIdx.x;
    const int tx = tid & 15, ty = tid >> 4;
    const int ar = tid >> 2, ac = (tid & 3) << 2;   // A: rows ar,+64 cols ac..+3
    const int br = tid >> 5, bc = (tid & 31) << 2;  // B: rows br,+8  cols bc..+3

    u64 acc[8][4];
#pragma unroll
    for (int i = 0; i < 8; i++)
#pragma unroll
        for (int j = 0; j < 4; j++) acc[i][j] = 0ULL;

    // ---- prologue: stage k-tile 0 into buffer 0 ----
    float4 areg[2];
#pragma unroll
    for (int p = 0; p < 2; p++) {
        areg[p] = *reinterpret_cast<const float4*>(&A[(size_t)(bm + ar + 64 * p) * 768 + ac]);
        cpa16(&Bs[0][br + 8 * p][bc], &Bm[(size_t)(br + 8 * p) * ldb + bn + bc]);
    }
    cpa_commit();
#pragma unroll
    for (int p = 0; p < 2; p++) {
        As[0][ac + 0][ar + 64 * p] = areg[p].x;
        As[0][ac + 1][ar + 64 * p] = areg[p].y;
        As[0][ac + 2][ar + 64 * p] = areg[p].z;
        As[0][ac + 3][ar + 64 * p] = areg[p].w;
    }
    cpa_wait0();
    __syncthreads();

    for (int kt = 0; kt < 48; kt++) {
        const int cb = kt & 1, nb = cb ^ 1;
        if (kt < 47) {
            const int k0n = (kt + 1) * 16;
#pragma unroll
            for (int p = 0; p < 2; p++) {
                areg[p] = *reinterpret_cast<const float4*>(
                    &A[(size_t)(bm + ar + 64 * p) * 768 + k0n + ac]);
                cpa16(&Bs[nb][br + 8 * p][bc],
                      &Bm[(size_t)(k0n + br + 8 * p) * ldb + bn + bc]);
            }
            cpa_commit();
        }
#pragma unroll
        for (int kk = 0; kk < 16; kk++) {
            float4 a0 = *reinterpret_cast<const float4*>(&As[cb][kk][ty * 8]);
            float4 a1 = *reinterpret_cast<const float4*>(&As[cb][kk][ty * 8 + 4]);
            float4 b0 = *reinterpret_cast<const float4*>(&Bs[cb][kk][tx * 4]);
            float4 b1 = *reinterpret_cast<const float4*>(&Bs[cb][kk][64 + tx * 4]);
            u64 bp0 = pk2(b0.x, b0.y), bp1 = pk2(b0.z, b0.w);
            u64 bp2 = pk2(b1.x, b1.y), bp3 = pk2(b1.z, b1.w);
            float av[8] = {a0.x, a0.y, a0.z, a0.w, a1.x, a1.y, a1.z, a1.w};
#pragma unroll
            for (int i = 0; i < 8; i++) {
                u64 ap = pk2(av[i], av[i]);
                fma2(acc[i][0], ap, bp0);
                fma2(acc[i][1], ap, bp1);
                fma2(acc[i][2], ap, bp2);
                fma2(acc[i][3], ap, bp3);
            }
        }
        if (kt < 47) {
#pragma unroll
            for (int p = 0; p < 2; p++) {
                As[nb][ac + 0][ar + 64 * p] = areg[p].x;
                As[nb][ac + 1][ar + 64 * p] = areg[p].y;
                As[nb][ac + 2][ar + 64 * p] = areg[p].z;
                As[nb][ac + 3][ar + 64 * p] = areg[p].w;
            }
        }
        cpa_wait0();
        __syncthreads();
    }

    if (mode == 0) {
#pragma unroll
        for (int g = 0; g < 2; g++) {
            const int col0 = bn + g * 64 + tx * 4;
            const int t   = col0 / 768;           // 0=q, 1=k, 2=v
            const int rem = col0 - t * 768;
            const int h   = rem >> 6;
            const int d0  = rem & 63;
            float* dst = (t == 0) ? g_q : (t == 1) ? g_k : g_v;
            const float sc = (t == 0) ? 0.125f : 1.0f;
            float4 bz = *reinterpret_cast<const float4*>(&bias[col0]);
#pragma unroll
            for (int i = 0; i < 8; i++) {
                int row = bm + ty * 8 + i;
                int b = row >> 11, n = row & 2047;
                float2 v0 = upk2(acc[i][2 * g]);
                float2 v1 = upk2(acc[i][2 * g + 1]);
                float4 o;
                o.x = (v0.x + bz.x) * sc;
                o.y = (v0.y + bz.y) * sc;
                o.z = (v1.x + bz.z) * sc;
                o.w = (v1.y + bz.w) * sc;
                *reinterpret_cast<float4*>(&dst[(((size_t)b * HH + h) * NN + n) * DH + d0]) = o;
            }
        }
    } else {
#pragma unroll
        for (int g = 0; g < 2; g++) {
            const int col0 = bn + g * 64 + tx * 4;
            float4 bz = *reinterpret_cast<const float4*>(&bias[col0]);
#pragma unroll
            for (int i = 0; i < 8; i++) {
                int row = bm + ty * 8 + i;
                float2 v0 = upk2(acc[i][2 * g]);
                float2 v1 = upk2(acc[i][2 * g + 1]);
                float4 o;
                o.x = v0.x + bz.x;
                o.y = v0.y + bz.y;
                o.z = v1.x + bz.z;
                o.w = v1.y + bz.w;
                *reinterpret_cast<float4*>(&outp[(size_t)row * 768 + col0]) = o;
            }
        }
    }
}

// =============================================================================
// Kernel 2: DynamicPositionBias MLP, fully fused.  16 rows per block, 192 thr.
// =============================================================================
__global__ __launch_bounds__(192) void dpb_kernel(const float* __restrict__ w_in,
                                                  const float* __restrict__ b_in,
                                                  const float* __restrict__ w_hid,
                                                  const float* __restrict__ b_hid,
                                                  const float* __restrict__ ln_g,
                                                  const float* __restrict__ ln_b,
                                                  const float* __restrict__ w_out,
                                                  const float* __restrict__ b_out)
{
    __shared__ float hbuf[16][DP];
    __shared__ float tmp[16][DP];
    __shared__ float mu_s[16], rs_s[16];
    const int j    = threadIdx.x;         // 0..191
    const int r0   = blockIdx.x * 16;
    const int warp = j >> 5, lane = j & 31;

    const float wi = w_in[j], bi = b_in[j];
#pragma unroll
    for (int r = 0; r < 16; r++) {
        float p = (float)(r0 + r) - 2047.0f;
        float sg = (p > 0.f) ? 1.f : ((p < 0.f) ? -1.f : 0.f);
        float pv = sg * logf(fabsf(p) + 1.f);
        tmp[r][j] = pv * wi + bi;
    }
    __syncthreads();

    for (int layer = 0; layer < 4; layer++) {
        for (int r = warp; r < 16; r += 6) {
            float s = 0.f, s2 = 0.f;
            for (int k = lane; k < DP; k += 32) {
                float v = tmp[r][k];
                s += v; s2 += v * v;
            }
#pragma unroll
            for (int off = 16; off > 0; off >>= 1) {
                s  += __shfl_xor_sync(0xffffffffu, s,  off);
                s2 += __shfl_xor_sync(0xffffffffu, s2, off);
            }
            if (lane == 0) {
                float mu = s * (1.0f / DP);
                float var = s2 * (1.0f / DP) - mu * mu;
                mu_s[r] = mu;
                rs_s[r] = rsqrtf(var + 1e-5f);
            }
        }
        __syncthreads();
        const float gj = ln_g[layer * DP + j], bj = ln_b[layer * DP + j];
#pragma unroll
        for (int r = 0; r < 16; r++) {
            float v = (tmp[r][j] - mu_s[r]) * rs_s[r] * gj + bj;
            hbuf[r][j] = v / (1.f + expf(-v));    // SiLU
        }
        __syncthreads();

        if (layer < 3) {
            float acc[16];
#pragma unroll
            for (int r = 0; r < 16; r++) acc[r] = 0.f;
            const float* Wp = w_hid + (size_t)layer * DP * DP + j;
            for (int k = 0; k < DP; k++) {
                float w = Wp[(size_t)k * DP];
#pragma unroll
                for (int r = 0; r < 16; r++) acc[r] = fmaf(hbuf[r][k], w, acc[r]);
            }
            const float bh = b_hid[layer * DP + j];
#pragma unroll
            for (int r = 0; r < 16; r++) tmp[r][j] = acc[r] + bh;
            __syncthreads();
        }
    }

    const int rr = j / 12, cc = j - rr * 12;
    float a = 0.f;
    for (int k = 0; k < DP; k++) a = fmaf(hbuf[rr][k], w_out[k * 12 + cc], a);
    const int row = r0 + rr;
    if (row < NPOS) g_vals[(size_t)row * HH + cc] = a + b_out[cc];
}

// =============================================================================
// Kernel 3: flash attention, 128 q x 64 k per tile, 256 threads, 8x4/thread,
// f32x2 FMAs.  K/V/bias tiles double-buffered: V via cp.async, K via register
// prefetch (transposed on store), bias via 1 register.
// =============================================================================
#define QS 132   // stride for 128-wide transposed tiles (Qs, Ps)
#define KS 68    // stride for 64-wide tiles (Ks, Vs)

__global__ __launch_bounds__(256, 1) void attn_kernel()
{
    extern __shared__ float sm[];
    float* Qs    = sm;                      // [64][132] transposed: Qs[d][m]
    float* Ps    = Qs + 64 * QS;            // [64][132] transposed: Ps[k][m]
    float* KsB   = Ps + 64 * QS;            // 2 x [64][68] transposed: Ks[d][n]
    float* VsB   = KsB + 2 * 64 * KS;       // 2 x [64][68] natural:    Vs[k][d]
    float* valsB = VsB + 2 * 64 * KS;       // 2 x [192] bias diagonal slices

    const int bh = blockIdx.y;
    const int b  = bh / HH, h = bh - b * HH;
    const int q0 = blockIdx.x * 128;
    const float* Qg = g_q + (size_t)bh * NN * DH;
    const float* Kg = g_k + (size_t)bh * NN * DH;
    const float* Vg = g_v + (size_t)bh * NN * DH;

    const int tid = threadIdx.x;
    const int tx = tid & 15, ty = tid >> 4;
    const int sm_m  = tid >> 4;            // 0..15 base row for staging
    const int sm_c4 = (tid & 15) << 2;     // 0..60 col group for staging

    // ---- load Q tile (128x64) transposed; q already scaled by Dh^-0.5 ----
#pragma unroll
    for (int i = 0; i < 8; i++) {
        int m = sm_m + i * 16;
        float4 v = *reinterpret_cast<const float4*>(&Qg[(size_t)(q0 + m) * DH + sm_c4]);
        Qs[(sm_c4 + 0) * QS + m] = v.x;
        Qs[(sm_c4 + 1) * QS + m] = v.y;
        Qs[(sm_c4 + 2) * QS + m] = v.z;
        Qs[(sm_c4 + 3) * QS + m] = v.w;
    }

    // ---- prologue: stage K/V/bias tile 0 into buffer 0 ----
    float4 kreg[4];
    float breg = 0.f;
#pragma unroll
    for (int i = 0; i < 4; i++) {
        int m = sm_m + i * 16;
        kreg[i] = *reinterpret_cast<const float4*>(&Kg[(size_t)m * DH + sm_c4]);
        cpa16(&VsB[m * KS + sm_c4], &Vg[(size_t)m * DH + sm_c4]);
    }
    cpa_commit();
    if (tid < 191) breg = g_vals[(size_t)(q0 + 2047 - 63 + tid) * HH + h];
#pragma unroll
    for (int i = 0; i < 4; i++) {
        int m = sm_m + i * 16;
        KsB[(sm_c4 + 0) * KS + m] = kreg[i].x;
        KsB[(sm_c4 + 1) * KS + m] = kreg[i].y;
        KsB[(sm_c4 + 2) * KS + m] = kreg[i].z;
        KsB[(sm_c4 + 3) * KS + m] = kreg[i].w;
    }
    if (tid < 191) valsB[tid] = breg;
    cpa_wait0();
    __syncthreads();

    float m_i[8], l_i[8];
    u64 oacc[8][2];
#pragma unroll
    for (int i = 0; i < 8; i++) {
        m_i[i] = -1e30f;
        l_i[i] = 0.f;
        oacc[i][0] = 0ULL;
        oacc[i][1] = 0ULL;
    }

    for (int kt = 0; kt < NN / 64; kt++) {
        const int cb = kt & 1, nb = cb ^ 1;
        const float* Ks     = KsB + cb * 64 * KS;
        const float* Vs     = VsB + cb * 64 * KS;
        const float* vals_s = valsB + cb * 192;

        // prefetch next K/V/bias tile
        if (kt < NN / 64 - 1) {
            const int kk0n = (kt + 1) * 64;
#pragma unroll
            for (int i = 0; i < 4; i++) {
                int m = sm_m + i * 16;
                kreg[i] = *reinterpret_cast<const float4*>(&Kg[(size_t)(kk0n + m) * DH + sm_c4]);
                cpa16(&VsB[nb * 64 * KS + m * KS + sm_c4],
                      &Vg[(size_t)(kk0n + m) * DH + sm_c4]);
            }
            cpa_commit();
            if (tid < 191) breg = g_vals[(size_t)(q0 - kk0n + 2047 - 63 + tid) * HH + h];
        }

        // S = Q @ K^T  (128x64), packed f32x2 accumulation
        u64 sacc[8][2];
#pragma unroll
        for (int i = 0; i < 8; i++) { sacc[i][0] = 0ULL; sacc[i][1] = 0ULL; }
#pragma unroll 4
        for (int d = 0; d < 64; d++) {
            float4 qa = *reinterpret_cast<const float4*>(&Qs[d * QS + ty * 8]);
            float4 qb = *reinterpret_cast<const float4*>(&Qs[d * QS + ty * 8 + 4]);
            float4 kb = *reinterpret_cast<const float4*>(&Ks[d * KS + tx * 4]);
            u64 bp0 = pk2(kb.x, kb.y), bp1 = pk2(kb.z, kb.w);
            float av[8] = {qa.x, qa.y, qa.z, qa.w, qb.x, qb.y, qb.z, qb.w};
#pragma unroll
            for (int i = 0; i < 8; i++) {
                u64 ap = pk2(av[i], av[i]);
                fma2(sacc[i][0], ap, bp0);
                fma2(sacc[i][1], ap, bp1);
            }
        }

        // + bias, online softmax (rows share 16 threads; shfl width 16)
#pragma unroll
        for (int i = 0; i < 8; i++) {
            float2 p0 = upk2(sacc[i][0]);
            float2 p1 = upk2(sacc[i][1]);
            float s0 = p0.x, s1 = p0.y, s2 = p1.x, s3 = p1.y;
            int moff = ty * 8 + i - tx * 4 + 63;
            s0 += vals_s[moff];
            s1 += vals_s[moff - 1];
            s2 += vals_s[moff - 2];
            s3 += vals_s[moff - 3];
            float rm = fmaxf(fmaxf(s0, s1), fmaxf(s2, s3));
#pragma unroll
            for (int off = 8; off > 0; off >>= 1)
                rm = fmaxf(rm, __shfl_xor_sync(0xffffffffu, rm, off, 16));
            float mnew  = fmaxf(m_i[i], rm);
            float alpha = __expf(m_i[i] - mnew);
            s0 = __expf(s0 - mnew);
            s1 = __expf(s1 - mnew);
            s2 = __expf(s2 - mnew);
            s3 = __expf(s3 - mnew);
            float rsum = s0 + s1 + s2 + s3;
#pragma unroll
            for (int off = 8; off > 0; off >>= 1)
                rsum += __shfl_xor_sync(0xffffffffu, rsum, off, 16);
            l_i[i] = l_i[i] * alpha + rsum;
            m_i[i] = mnew;
            u64 alp = pk2(alpha, alpha);
            mul2(oacc[i][0], alp);
            mul2(oacc[i][1], alp);
            // write P transposed for the PV GEMM
            Ps[(tx * 4 + 0) * QS + ty * 8 + i] = s0;
            Ps[(tx * 4 + 1) * QS + ty * 8 + i] = s1;
            Ps[(tx * 4 + 2) * QS + ty * 8 + i] = s2;
            Ps[(tx * 4 + 3) * QS + ty * 8 + i] = s3;
        }

        // store prefetched K/bias into the next buffer (safe: last read of that
        // buffer finished before the previous iteration's final barrier)
        if (kt < NN / 64 - 1) {
            float* Ksn = KsB + nb * 64 * KS;
#pragma unroll
            for (int i = 0; i < 4; i++) {
                int m = sm_m + i * 16;
                Ksn[(sm_c4 + 0) * KS + m] = kreg[i].x;
                Ksn[(sm_c4 + 1) * KS + m] = kreg[i].y;
                Ksn[(sm_c4 + 2) * KS + m] = kreg[i].z;
                Ksn[(sm_c4 + 3) * KS + m] = kreg[i].w;
            }
            if (tid < 191) valsB[nb * 192 + tid] = breg;
        }
        __syncthreads();   // P + next-K visible

        // O += P @ V  (128x64 += 128x64 @ 64x64), packed f32x2
#pragma unroll 4
        for (int k = 0; k < 64; k++) {
            float4 pa = *reinterpret_cast<const float4*>(&Ps[k * QS + ty * 8]);
            float4 pb = *reinterpret_cast<const float4*>(&Ps[k * QS + ty * 8 + 4]);
            float4 vb = *reinterpret_cast<const float4*>(&Vs[k * KS + tx * 4]);
            u64 bp0 = pk2(vb.x, vb.y), bp1 = pk2(vb.z, vb.w);
            float av[8] = {pa.x, pa.y, pa.z, pa.w, pb.x, pb.y, pb.z, pb.w};
#pragma unroll
            for (int i = 0; i < 8; i++) {
                u64 ap = pk2(av[i], av[i]);
                fma2(oacc[i][0], ap, bp0);
                fma2(oacc[i][1], ap, bp1);
            }
        }
        cpa_wait0();       // next V tile landed
        __syncthreads();   // all warps done with cb buffers
    }

    // normalize and store to [b,n,h*64+d] for the output projection
#pragma unroll
    for (int i = 0; i < 8; i++) {
        float inv = 1.0f / l_i[i];
        float2 v0 = upk2(oacc[i][0]);
        float2 v1 = upk2(oacc[i][1]);
        float4 o;
        o.x = v0.x * inv;
        o.y = v0.y * inv;
        o.z = v1.x * inv;
        o.w = v1.y * inv;
        size_t row = (size_t)b * NN + q0 + ty * 8 + i;
        *reinterpret_cast<float4*>(&g_o[row * DD + h * DH + tx * 4]) = o;
    }
}

// =============================================================================
extern "C" void kernel_launch(void* const* d_in, const int* in_sizes, int n_in,
                              void* d_out, int out_size)
{
    const float* x         = (const float*)d_in[0];
    const float* qkv_w     = (const float*)d_in[1];
    const float* qkv_b     = (const float*)d_in[2];
    const float* out_w     = (const float*)d_in[3];
    const float* out_b     = (const float*)d_in[4];
    const float* dpb_w_in  = (const float*)d_in[5];
    const float* dpb_b_in  = (const float*)d_in[6];
    const float* dpb_w_hid = (const float*)d_in[7];
    const float* dpb_b_hid = (const float*)d_in[8];
    const float* dpb_ln_g  = (const float*)d_in[9];
    const float* dpb_ln_b  = (const float*)d_in[10];
    const float* dpb_w_out = (const float*)d_in[11];
    const float* dpb_b_out = (const float*)d_in[12];
    float* out = (float*)d_out;

    const int attn_smem =
        (2 * 64 * QS + 2 * 2 * 64 * KS + 2 * 192) * (int)sizeof(float);  // ~139 KB
    cudaFuncSetAttribute(attn_kernel, cudaFuncAttributeMaxDynamicSharedMemorySize,
                         attn_smem);

    dpb_kernel<<<256, 192>>>(dpb_w_in, dpb_b_in, dpb_w_hid, dpb_b_hid,
                             dpb_ln_g, dpb_ln_b, dpb_w_out, dpb_b_out);
    big_gemm<<<dim3(18, 32), 256>>>(x, qkv_w, 2304, 0, qkv_b, nullptr);
    attn_kernel<<<dim3(16, 24), 256, attn_smem>>>();
    big_gemm<<<dim3(6, 32), 256>>>(nullptr, out_w, 768, 1, out_b, out);
}

// round 8
// speedup vs baseline: 1.2624x; 1.0817x over previous
#include <cuda_runtime.h>

// Problem constants (fixed shapes)
#define BB   2
#define NN   2048
#define DD   768
#define HH   12
#define DH   64
#define DP   192
#define NPOS 4095   // 2*N - 1

typedef unsigned long long u64;

// ---------------- f32x2 packed-math helpers (FFMA2 path, sm_103a) -------------
__device__ __forceinline__ u64 pk2(float lo, float hi) {
    u64 r; asm("mov.b64 %0, {%1, %2};" : "=l"(r) : "f"(lo), "f"(hi)); return r;
}
__device__ __forceinline__ float2 upk2(u64 v) {
    float2 r; asm("mov.b64 {%0, %1}, %2;" : "=f"(r.x), "=f"(r.y) : "l"(v)); return r;
}
__device__ __forceinline__ void fma2(u64 &d, u64 a, u64 b) {
    asm("fma.rn.f32x2 %0, %1, %2, %0;" : "+l"(d) : "l"(a), "l"(b));
}
__device__ __forceinline__ void mul2(u64 &d, u64 a) {
    asm("mul.rn.f32x2 %0, %0, %1;" : "+l"(d) : "l"(a));
}

// ---------------- cp.async helpers (LDGSTS) -----------------------------------
__device__ __forceinline__ void cpa16(void* smem_dst, const void* gmem_src) {
    unsigned s = (unsigned)__cvta_generic_to_shared(smem_dst);
    asm volatile("cp.async.cg.shared.global [%0], [%1], 16;" :: "r"(s), "l"(gmem_src));
}
__device__ __forceinline__ void cpa_commit() {
    asm volatile("cp.async.commit_group;");
}
__device__ __forceinline__ void cpa_wait0() {
    asm volatile("cp.async.wait_group 0;");
}

// ---------------- scratch (device globals; no allocations allowed) ------------
__device__ float g_q[(size_t)BB*HH*NN*DH];     // [b,h,n,d], pre-scaled by 1/8
__device__ float g_k[(size_t)BB*HH*NN*DH];
__device__ float g_v[(size_t)BB*HH*NN*DH];
__device__ float g_vals[(size_t)NPOS*HH];      // DPB MLP output [2N-1, H]
__device__ float g_o[(size_t)BB*NN*DD];        // attention output [b,n,h*64+d]

// =============================================================================
// Kernel 1: 128x128-tile SGEMM, f32x2 FMAs, double-buffered smem.
// B tiles arrive via cp.async (no transpose needed); A tiles prefetched via
// registers (transposed on store).  256 threads, 8x8/thread.
// mode 0: A = x,  B = qkv_w [768,2304], scatter to g_q/g_k/g_v (q*0.125)
// mode 1: A = g_o (device symbol resolved in-kernel), B = out_w, write outp.
// =============================================================================
__global__ __launch_bounds__(256, 2) void big_gemm(const float* __restrict__ Ain,
                                                   const float* __restrict__ Bm,
                                                   int ldb, int mode,
                                                   const float* __restrict__ bias,
                                                   float* __restrict__ outp)
{
    __shared__ float As[2][16][132];   // transposed: As[buf][k][m]
    __shared__ float Bs[2][16][132];   // natural:    Bs[buf][k][n]
    const float* A = (mode == 1) ? g_o : Ain;
    const int bm = blockIdx.y * 128;
    const int bn = blockIdx.x * 128;
    const int tid = threadIdx.x;
    const int tx = tid & 15, ty = tid >> 4;
    const int ar = tid >> 2, ac = (tid & 3) << 2;   // A: rows ar,+64 cols ac..+3
    const int br = tid >> 5, bc = (tid & 31) << 2;  // B: rows br,+8  cols bc..+3

    u64 acc[8][4];
#pragma unroll
    for (int i = 0; i < 8; i++)
#pragma unroll
        for (int j = 0; j < 4; j++) acc[i][j] = 0ULL;

    // ---- prologue: stage k-tile 0 into buffer 0 ----
    float4 areg[2];
#pragma unroll
    for (int p = 0; p < 2; p++) {
        areg[p] = *reinterpret_cast<const float4*>(&A[(size_t)(bm + ar + 64 * p) * 768 + ac]);
        cpa16(&Bs[0][br + 8 * p][bc], &Bm[(size_t)(br + 8 * p) * ldb + bn + bc]);
    }
    cpa_commit();
#pragma unroll
    for (int p = 0; p < 2; p++) {
        As[0][ac + 0][ar + 64 * p] = areg[p].x;
        As[0][ac + 1][ar + 64 * p] = areg[p].y;
        As[0][ac + 2][ar + 64 * p] = areg[p].z;
        As[0][ac + 3][ar + 64 * p] = areg[p].w;
    }
    cpa_wait0();
    __syncthreads();

    for (int kt = 0; kt < 48; kt++) {
        const int cb = kt & 1, nb = cb ^ 1;
        if (kt < 47) {
            const int k0n = (kt + 1) * 16;
#pragma unroll
            for (int p = 0; p < 2; p++) {
                areg[p] = *reinterpret_cast<const float4*>(
                    &A[(size_t)(bm + ar + 64 * p) * 768 + k0n + ac]);
                cpa16(&Bs[nb][br + 8 * p][bc],
                      &Bm[(size_t)(k0n + br + 8 * p) * ldb + bn + bc]);
            }
            cpa_commit();
        }
#pragma unroll
        for (int kk = 0; kk < 16; kk++) {
            float4 a0 = *reinterpret_cast<const float4*>(&As[cb][kk][ty * 8]);
            float4 a1 = *reinterpret_cast<const float4*>(&As[cb][kk][ty * 8 + 4]);
            float4 b0 = *reinterpret_cast<const float4*>(&Bs[cb][kk][tx * 4]);
            float4 b1 = *reinterpret_cast<const float4*>(&Bs[cb][kk][64 + tx * 4]);
            u64 bp0 = pk2(b0.x, b0.y), bp1 = pk2(b0.z, b0.w);
            u64 bp2 = pk2(b1.x, b1.y), bp3 = pk2(b1.z, b1.w);
            float av[8] = {a0.x, a0.y, a0.z, a0.w, a1.x, a1.y, a1.z, a1.w};
#pragma unroll
            for (int i = 0; i < 8; i++) {
                u64 ap = pk2(av[i], av[i]);
                fma2(acc[i][0], ap, bp0);
                fma2(acc[i][1], ap, bp1);
                fma2(acc[i][2], ap, bp2);
                fma2(acc[i][3], ap, bp3);
            }
        }
        if (kt < 47) {
#pragma unroll
            for (int p = 0; p < 2; p++) {
                As[nb][ac + 0][ar + 64 * p] = areg[p].x;
                As[nb][ac + 1][ar + 64 * p] = areg[p].y;
                As[nb][ac + 2][ar + 64 * p] = areg[p].z;
                As[nb][ac + 3][ar + 64 * p] = areg[p].w;
            }
        }
        cpa_wait0();
        __syncthreads();
    }

    if (mode == 0) {
#pragma unroll
        for (int g = 0; g < 2; g++) {
            const int col0 = bn + g * 64 + tx * 4;
            const int t   = col0 / 768;           // 0=q, 1=k, 2=v
            const int rem = col0 - t * 768;
            const int h   = rem >> 6;
            const int d0  = rem & 63;
            float* dst = (t == 0) ? g_q : (t == 1) ? g_k : g_v;
            const float sc = (t == 0) ? 0.125f : 1.0f;
            float4 bz = *reinterpret_cast<const float4*>(&bias[col0]);
#pragma unroll
            for (int i = 0; i < 8; i++) {
                int row = bm + ty * 8 + i;
                int b = row >> 11, n = row & 2047;
                float2 v0 = upk2(acc[i][2 * g]);
                float2 v1 = upk2(acc[i][2 * g + 1]);
                float4 o;
                o.x = (v0.x + bz.x) * sc;
                o.y = (v0.y + bz.y) * sc;
                o.z = (v1.x + bz.z) * sc;
                o.w = (v1.y + bz.w) * sc;
                *reinterpret_cast<float4*>(&dst[(((size_t)b * HH + h) * NN + n) * DH + d0]) = o;
            }
        }
    } else {
#pragma unroll
        for (int g = 0; g < 2; g++) {
            const int col0 = bn + g * 64 + tx * 4;
            float4 bz = *reinterpret_cast<const float4*>(&bias[col0]);
#pragma unroll
            for (int i = 0; i < 8; i++) {
                int row = bm + ty * 8 + i;
                float2 v0 = upk2(acc[i][2 * g]);
                float2 v1 = upk2(acc[i][2 * g + 1]);
                float4 o;
                o.x = v0.x + bz.x;
                o.y = v0.y + bz.y;
                o.z = v1.x + bz.z;
                o.w = v1.y + bz.w;
                *reinterpret_cast<float4*>(&outp[(size_t)row * 768 + col0]) = o;
            }
        }
    }
}

// =============================================================================
// Kernel 2: DynamicPositionBias MLP, fully fused.  16 rows per block, 192 thr.
// =============================================================================
__global__ __launch_bounds__(192) void dpb_kernel(const float* __restrict__ w_in,
                                                  const float* __restrict__ b_in,
                                                  const float* __restrict__ w_hid,
                                                  const float* __restrict__ b_hid,
                                                  const float* __restrict__ ln_g,
                                                  const float* __restrict__ ln_b,
                                                  const float* __restrict__ w_out,
                                                  const float* __restrict__ b_out)
{
    __shared__ float hbuf[16][DP];
    __shared__ float tmp[16][DP];
    __shared__ float mu_s[16], rs_s[16];
    const int j    = threadIdx.x;         // 0..191
    const int r0   = blockIdx.x * 16;
    const int warp = j >> 5, lane = j & 31;

    const float wi = w_in[j], bi = b_in[j];
#pragma unroll
    for (int r = 0; r < 16; r++) {
        float p = (float)(r0 + r) - 2047.0f;
        float sg = (p > 0.f) ? 1.f : ((p < 0.f) ? -1.f : 0.f);
        float pv = sg * logf(fabsf(p) + 1.f);
        tmp[r][j] = pv * wi + bi;
    }
    __syncthreads();

    for (int layer = 0; layer < 4; layer++) {
        for (int r = warp; r < 16; r += 6) {
            float s = 0.f, s2 = 0.f;
            for (int k = lane; k < DP; k += 32) {
                float v = tmp[r][k];
                s += v; s2 += v * v;
            }
#pragma unroll
            for (int off = 16; off > 0; off >>= 1) {
                s  += __shfl_xor_sync(0xffffffffu, s,  off);
                s2 += __shfl_xor_sync(0xffffffffu, s2, off);
            }
            if (lane == 0) {
                float mu = s * (1.0f / DP);
                float var = s2 * (1.0f / DP) - mu * mu;
                mu_s[r] = mu;
                rs_s[r] = rsqrtf(var + 1e-5f);
            }
        }
        __syncthreads();
        const float gj = ln_g[layer * DP + j], bj = ln_b[layer * DP + j];
#pragma unroll
        for (int r = 0; r < 16; r++) {
            float v = (tmp[r][j] - mu_s[r]) * rs_s[r] * gj + bj;
            hbuf[r][j] = v / (1.f + expf(-v));    // SiLU
        }
        __syncthreads();

        if (layer < 3) {
            float acc[16];
#pragma unroll
            for (int r = 0; r < 16; r++) acc[r] = 0.f;
            const float* Wp = w_hid + (size_t)layer * DP * DP + j;
            for (int k = 0; k < DP; k++) {
                float w = Wp[(size_t)k * DP];
#pragma unroll
                for (int r = 0; r < 16; r++) acc[r] = fmaf(hbuf[r][k], w, acc[r]);
            }
            const float bh = b_hid[layer * DP + j];
#pragma unroll
            for (int r = 0; r < 16; r++) tmp[r][j] = acc[r] + bh;
            __syncthreads();
        }
    }

    const int rr = j / 12, cc = j - rr * 12;
    float a = 0.f;
    for (int k = 0; k < DP; k++) a = fmaf(hbuf[rr][k], w_out[k * 12 + cc], a);
    const int row = r0 + rr;
    if (row < NPOS) g_vals[(size_t)row * HH + cc] = a + b_out[cc];
}

// =============================================================================
// Kernel 3: flash attention, 128 q x 64 k per tile, 256 threads, 8x4/thread,
// f32x2 FMAs.  Single-buffered K/V/bias tiles (103 KB smem) so TWO CTAs fit
// per SM — 16 warps/SM hides LDS/global latency better than prefetch did.
// =============================================================================
#define QS 132   // stride for 128-wide transposed tiles (Qs, Ps)
#define KS 68    // stride for 64-wide tiles (Ks, Vs)

__global__ __launch_bounds__(256, 2) void attn_kernel()
{
    extern __shared__ float sm[];
    float* Qs     = sm;                     // [64][132] transposed: Qs[d][m]
    float* Ps     = Qs + 64 * QS;           // [64][132] transposed: Ps[k][m]
    float* Ks     = Ps + 64 * QS;           // [64][68]  transposed: Ks[d][n]
    float* Vs     = Ks + 64 * KS;           // [64][68]  natural:    Vs[k][d]
    float* vals_s = Vs + 64 * KS;           // [192] bias diagonal slice

    const int bh = blockIdx.y;
    const int b  = bh / HH, h = bh - b * HH;
    const int q0 = blockIdx.x * 128;
    const float* Qg = g_q + (size_t)bh * NN * DH;
    const float* Kg = g_k + (size_t)bh * NN * DH;
    const float* Vg = g_v + (size_t)bh * NN * DH;

    const int tid = threadIdx.x;
    const int tx = tid & 15, ty = tid >> 4;
    const int sm_m  = tid >> 4;            // 0..15 base row for staging
    const int sm_c4 = (tid & 15) << 2;     // 0..60 col group for staging

    // ---- load Q tile (128x64) transposed; q already scaled by Dh^-0.5 ----
#pragma unroll
    for (int i = 0; i < 8; i++) {
        int m = sm_m + i * 16;
        float4 v = *reinterpret_cast<const float4*>(&Qg[(size_t)(q0 + m) * DH + sm_c4]);
        Qs[(sm_c4 + 0) * QS + m] = v.x;
        Qs[(sm_c4 + 1) * QS + m] = v.y;
        Qs[(sm_c4 + 2) * QS + m] = v.z;
        Qs[(sm_c4 + 3) * QS + m] = v.w;
    }

    float m_i[8], l_i[8];
    u64 oacc[8][2];
#pragma unroll
    for (int i = 0; i < 8; i++) {
        m_i[i] = -1e30f;
        l_i[i] = 0.f;
        oacc[i][0] = 0ULL;
        oacc[i][1] = 0ULL;
    }

    for (int kt = 0; kt < NN / 64; kt++) {
        const int kk0 = kt * 64;
        // buffer is free here: kt==0 trivially; kt>0 by the sync after PV below
        // stage K (transposed via regs), V (cp.async), bias slice
#pragma unroll
        for (int i = 0; i < 4; i++) {
            int m = sm_m + i * 16;
            float4 kv = *reinterpret_cast<const float4*>(&Kg[(size_t)(kk0 + m) * DH + sm_c4]);
            cpa16(&Vs[m * KS + sm_c4], &Vg[(size_t)(kk0 + m) * DH + sm_c4]);
            Ks[(sm_c4 + 0) * KS + m] = kv.x;
            Ks[(sm_c4 + 1) * KS + m] = kv.y;
            Ks[(sm_c4 + 2) * KS + m] = kv.z;
            Ks[(sm_c4 + 3) * KS + m] = kv.w;
        }
        cpa_commit();
        if (tid < 191) vals_s[tid] = g_vals[(size_t)(q0 - kk0 + 2047 - 63 + tid) * HH + h];
        cpa_wait0();
        __syncthreads();

        // S = Q @ K^T  (128x64), packed f32x2 accumulation
        u64 sacc[8][2];
#pragma unroll
        for (int i = 0; i < 8; i++) { sacc[i][0] = 0ULL; sacc[i][1] = 0ULL; }
#pragma unroll 4
        for (int d = 0; d < 64; d++) {
            float4 qa = *reinterpret_cast<const float4*>(&Qs[d * QS + ty * 8]);
            float4 qb = *reinterpret_cast<const float4*>(&Qs[d * QS + ty * 8 + 4]);
            float4 kb = *reinterpret_cast<const float4*>(&Ks[d * KS + tx * 4]);
            u64 bp0 = pk2(kb.x, kb.y), bp1 = pk2(kb.z, kb.w);
            float av[8] = {qa.x, qa.y, qa.z, qa.w, qb.x, qb.y, qb.z, qb.w};
#pragma unroll
            for (int i = 0; i < 8; i++) {
                u64 ap = pk2(av[i], av[i]);
                fma2(sacc[i][0], ap, bp0);
                fma2(sacc[i][1], ap, bp1);
            }
        }

        // + bias, online softmax (rows share 16 threads; shfl width 16)
#pragma unroll
        for (int i = 0; i < 8; i++) {
            float2 p0 = upk2(sacc[i][0]);
            float2 p1 = upk2(sacc[i][1]);
            float s0 = p0.x, s1 = p0.y, s2 = p1.x, s3 = p1.y;
            int moff = ty * 8 + i - tx * 4 + 63;
            s0 += vals_s[moff];
            s1 += vals_s[moff - 1];
            s2 += vals_s[moff - 2];
            s3 += vals_s[moff - 3];
            float rm = fmaxf(fmaxf(s0, s1), fmaxf(s2, s3));
#pragma unroll
            for (int off = 8; off > 0; off >>= 1)
                rm = fmaxf(rm, __shfl_xor_sync(0xffffffffu, rm, off, 16));
            float mnew  = fmaxf(m_i[i], rm);
            float alpha = __expf(m_i[i] - mnew);
            s0 = __expf(s0 - mnew);
            s1 = __expf(s1 - mnew);
            s2 = __expf(s2 - mnew);
            s3 = __expf(s3 - mnew);
            float rsum = s0 + s1 + s2 + s3;
#pragma unroll
            for (int off = 8; off > 0; off >>= 1)
                rsum += __shfl_xor_sync(0xffffffffu, rsum, off, 16);
            l_i[i] = l_i[i] * alpha + rsum;
            m_i[i] = mnew;
            u64 alp = pk2(alpha, alpha);
            mul2(oacc[i][0], alp);
            mul2(oacc[i][1], alp);
            // write P transposed for the PV GEMM
            Ps[(tx * 4 + 0) * QS + ty * 8 + i] = s0;
            Ps[(tx * 4 + 1) * QS + ty * 8 + i] = s1;
            Ps[(tx * 4 + 2) * QS + ty * 8 + i] = s2;
            Ps[(tx * 4 + 3) * QS + ty * 8 + i] = s3;
        }
        __syncthreads();   // Ps visible to all warps

        // O += P @ V  (128x64 += 128x64 @ 64x64), packed f32x2
#pragma unroll 4
        for (int k = 0; k < 64; k++) {
            float4 pa = *reinterpret_cast<const float4*>(&Ps[k * QS + ty * 8]);
            float4 pb = *reinterpret_cast<const float4*>(&Ps[k * QS + ty * 8 + 4]);
            float4 vb = *reinterpret_cast<const float4*>(&Vs[k * KS + tx * 4]);
            u64 bp0 = pk2(vb.x, vb.y), bp1 = pk2(vb.z, vb.w);
            float av[8] = {pa.x, pa.y, pa.z, pa.w, pb.x, pb.y, pb.z, pb.w};
#pragma unroll
            for (int i = 0; i < 8; i++) {
                u64 ap = pk2(av[i], av[i]);
                fma2(oacc[i][0], ap, bp0);
                fma2(oacc[i][1], ap, bp1);
            }
        }
        __syncthreads();   // done reading Ks/Vs/vals before next stage
    }

    // normalize and store to [b,n,h*64+d] for the output projection
#pragma unroll
    for (int i = 0; i < 8; i++) {
        float inv = 1.0f / l_i[i];
        float2 v0 = upk2(oacc[i][0]);
        float2 v1 = upk2(oacc[i][1]);
        float4 o;
        o.x = v0.x * inv;
        o.y = v0.y * inv;
        o.z = v1.x * inv;
        o.w = v1.y * inv;
        size_t row = (size_t)b * NN + q0 + ty * 8 + i;
        *reinterpret_cast<float4*>(&g_o[row * DD + h * DH + tx * 4]) = o;
    }
}

// =============================================================================
extern "C" void kernel_launch(void* const* d_in, const int* in_sizes, int n_in,
                              void* d_out, int out_size)
{
    const float* x         = (const float*)d_in[0];
    const float* qkv_w     = (const float*)d_in[1];
    const float* qkv_b     = (const float*)d_in[2];
    const float* out_w     = (const float*)d_in[3];
    const float* out_b     = (const float*)d_in[4];
    const float* dpb_w_in  = (const float*)d_in[5];
    const float* dpb_b_in  = (const float*)d_in[6];
    const float* dpb_w_hid = (const float*)d_in[7];
    const float* dpb_b_hid = (const float*)d_in[8];
    const float* dpb_ln_g  = (const float*)d_in[9];
    const float* dpb_ln_b  = (const float*)d_in[10];
    const float* dpb_w_out = (const float*)d_in[11];
    const float* dpb_b_out = (const float*)d_in[12];
    float* out = (float*)d_out;

    // single-buffered attention smem: 2*64*132 + 2*64*68 + 192 floats = ~103 KB
    const int attn_smem =
        (2 * 64 * QS + 2 * 64 * KS + 192) * (int)sizeof(float);
    cudaFuncSetAttribute(attn_kernel, cudaFuncAttributeMaxDynamicSharedMemorySize,
                         attn_smem);

    dpb_kernel<<<256, 192>>>(dpb_w_in, dpb_b_in, dpb_w_hid, dpb_b_hid,
                             dpb_ln_g, dpb_ln_b, dpb_w_out, dpb_b_out);
    big_gemm<<<dim3(18, 32), 256>>>(x, qkv_w, 2304, 0, qkv_b, nullptr);
    attn_kernel<<<dim3(16, 24), 256, attn_smem>>>();
    big_gemm<<<dim3(6, 32), 256>>>(nullptr, out_w, 768, 1, out_b, out);
}

// round 9
// speedup vs baseline: 1.2709x; 1.0067x over previous
#include <cuda_runtime.h>

// Problem constants (fixed shapes)
#define BB   2
#define NN   2048
#define DD   768
#define HH   12
#define DH   64
#define DP   192
#define NPOS 4095   // 2*N - 1

typedef unsigned long long u64;

// ---------------- f32x2 packed-math helpers (FFMA2 path, sm_103a) -------------
__device__ __forceinline__ u64 pk2(float lo, float hi) {
    u64 r; asm("mov.b64 %0, {%1, %2};" : "=l"(r) : "f"(lo), "f"(hi)); return r;
}
__device__ __forceinline__ float2 upk2(u64 v) {
    float2 r; asm("mov.b64 {%0, %1}, %2;" : "=f"(r.x), "=f"(r.y) : "l"(v)); return r;
}
__device__ __forceinline__ void fma2(u64 &d, u64 a, u64 b) {
    asm("fma.rn.f32x2 %0, %1, %2, %0;" : "+l"(d) : "l"(a), "l"(b));
}
__device__ __forceinline__ void mul2(u64 &d, u64 a) {
    asm("mul.rn.f32x2 %0, %0, %1;" : "+l"(d) : "l"(a));
}

// ---------------- cp.async helpers (LDGSTS) -----------------------------------
__device__ __forceinline__ void cpa16(void* smem_dst, const void* gmem_src) {
    unsigned s = (unsigned)__cvta_generic_to_shared(smem_dst);
    asm volatile("cp.async.cg.shared.global [%0], [%1], 16;" :: "r"(s), "l"(gmem_src));
}
__device__ __forceinline__ void cpa_commit() {
    asm volatile("cp.async.commit_group;");
}
__device__ __forceinline__ void cpa_wait0() {
    asm volatile("cp.async.wait_group 0;");
}

// ---------------- scratch (device globals; no allocations allowed) ------------
__device__ float g_q[(size_t)BB*HH*NN*DH];     // [b,h,n,d], pre-scaled by 1/8
__device__ float g_k[(size_t)BB*HH*NN*DH];
__device__ float g_v[(size_t)BB*HH*NN*DH];
__device__ float g_vals[(size_t)NPOS*HH];      // DPB MLP output [2N-1, H]
__device__ float g_o[(size_t)BB*NN*DD];        // attention output [b,n,h*64+d]

// =============================================================================
// Kernel 1: 128x128-tile SGEMM, f32x2 FMAs, double-buffered smem.
// B tiles arrive via cp.async (no transpose needed); A tiles prefetched via
// registers (transposed on store).  256 threads, 8x8/thread.
// mode 0: A = x,  B = qkv_w [768,2304], scatter to g_q/g_k/g_v (q*0.125)
// mode 1: A = g_o (device symbol resolved in-kernel), B = out_w, write outp.
// =============================================================================
__global__ __launch_bounds__(256, 2) void big_gemm(const float* __restrict__ Ain,
                                                   const float* __restrict__ Bm,
                                                   int ldb, int mode,
                                                   const float* __restrict__ bias,
                                                   float* __restrict__ outp)
{
    __shared__ float As[2][16][132];   // transposed: As[buf][k][m]
    __shared__ float Bs[2][16][132];   // natural:    Bs[buf][k][n]
    const float* A = (mode == 1) ? g_o : Ain;
    const int bm = blockIdx.y * 128;
    const int bn = blockIdx.x * 128;
    const int tid = threadIdx.x;
    const int tx = tid & 15, ty = tid >> 4;
    const int ar = tid >> 2, ac = (tid & 3) << 2;   // A: rows ar,+64 cols ac..+3
    const int br = tid >> 5, bc = (tid & 31) << 2;  // B: rows br,+8  cols bc..+3

    u64 acc[8][4];
#pragma unroll
    for (int i = 0; i < 8; i++)
#pragma unroll
        for (int j = 0; j < 4; j++) acc[i][j] = 0ULL;

    // ---- prologue: stage k-tile 0 into buffer 0 ----
    float4 areg[2];
#pragma unroll
    for (int p = 0; p < 2; p++) {
        areg[p] = *reinterpret_cast<const float4*>(&A[(size_t)(bm + ar + 64 * p) * 768 + ac]);
        cpa16(&Bs[0][br + 8 * p][bc], &Bm[(size_t)(br + 8 * p) * ldb + bn + bc]);
    }
    cpa_commit();
#pragma unroll
    for (int p = 0; p < 2; p++) {
        As[0][ac + 0][ar + 64 * p] = areg[p].x;
        As[0][ac + 1][ar + 64 * p] = areg[p].y;
        As[0][ac + 2][ar + 64 * p] = areg[p].z;
        As[0][ac + 3][ar + 64 * p] = areg[p].w;
    }
    cpa_wait0();
    __syncthreads();

    for (int kt = 0; kt < 48; kt++) {
        const int cb = kt & 1, nb = cb ^ 1;
        if (kt < 47) {
            const int k0n = (kt + 1) * 16;
#pragma unroll
            for (int p = 0; p < 2; p++) {
                areg[p] = *reinterpret_cast<const float4*>(
                    &A[(size_t)(bm + ar + 64 * p) * 768 + k0n + ac]);
                cpa16(&Bs[nb][br + 8 * p][bc],
                      &Bm[(size_t)(k0n + br + 8 * p) * ldb + bn + bc]);
            }
            cpa_commit();
        }
#pragma unroll
        for (int kk = 0; kk < 16; kk++) {
            float4 a0 = *reinterpret_cast<const float4*>(&As[cb][kk][ty * 8]);
            float4 a1 = *reinterpret_cast<const float4*>(&As[cb][kk][ty * 8 + 4]);
            float4 b0 = *reinterpret_cast<const float4*>(&Bs[cb][kk][tx * 4]);
            float4 b1 = *reinterpret_cast<const float4*>(&Bs[cb][kk][64 + tx * 4]);
            u64 bp0 = pk2(b0.x, b0.y), bp1 = pk2(b0.z, b0.w);
            u64 bp2 = pk2(b1.x, b1.y), bp3 = pk2(b1.z, b1.w);
            float av[8] = {a0.x, a0.y, a0.z, a0.w, a1.x, a1.y, a1.z, a1.w};
#pragma unroll
            for (int i = 0; i < 8; i++) {
                u64 ap = pk2(av[i], av[i]);
                fma2(acc[i][0], ap, bp0);
                fma2(acc[i][1], ap, bp1);
                fma2(acc[i][2], ap, bp2);
                fma2(acc[i][3], ap, bp3);
            }
        }
        if (kt < 47) {
#pragma unroll
            for (int p = 0; p < 2; p++) {
                As[nb][ac + 0][ar + 64 * p] = areg[p].x;
                As[nb][ac + 1][ar + 64 * p] = areg[p].y;
                As[nb][ac + 2][ar + 64 * p] = areg[p].z;
                As[nb][ac + 3][ar + 64 * p] = areg[p].w;
            }
        }
        cpa_wait0();
        __syncthreads();
    }

    if (mode == 0) {
#pragma unroll
        for (int g = 0; g < 2; g++) {
            const int col0 = bn + g * 64 + tx * 4;
            const int t   = col0 / 768;           // 0=q, 1=k, 2=v
            const int rem = col0 - t * 768;
            const int h   = rem >> 6;
            const int d0  = rem & 63;
            float* dst = (t == 0) ? g_q : (t == 1) ? g_k : g_v;
            const float sc = (t == 0) ? 0.125f : 1.0f;
            float4 bz = *reinterpret_cast<const float4*>(&bias[col0]);
#pragma unroll
            for (int i = 0; i < 8; i++) {
                int row = bm + ty * 8 + i;
                int b = row >> 11, n = row & 2047;
                float2 v0 = upk2(acc[i][2 * g]);
                float2 v1 = upk2(acc[i][2 * g + 1]);
                float4 o;
                o.x = (v0.x + bz.x) * sc;
                o.y = (v0.y + bz.y) * sc;
                o.z = (v1.x + bz.z) * sc;
                o.w = (v1.y + bz.w) * sc;
                *reinterpret_cast<float4*>(&dst[(((size_t)b * HH + h) * NN + n) * DH + d0]) = o;
            }
        }
    } else {
#pragma unroll
        for (int g = 0; g < 2; g++) {
            const int col0 = bn + g * 64 + tx * 4;
            float4 bz = *reinterpret_cast<const float4*>(&bias[col0]);
#pragma unroll
            for (int i = 0; i < 8; i++) {
                int row = bm + ty * 8 + i;
                float2 v0 = upk2(acc[i][2 * g]);
                float2 v1 = upk2(acc[i][2 * g + 1]);
                float4 o;
                o.x = v0.x + bz.x;
                o.y = v0.y + bz.y;
                o.z = v1.x + bz.z;
                o.w = v1.y + bz.w;
                *reinterpret_cast<float4*>(&outp[(size_t)row * 768 + col0]) = o;
            }
        }
    }
}

// =============================================================================
// Kernel 2: DynamicPositionBias MLP, fully fused.  16 rows per block, 192 thr.
// =============================================================================
__global__ __launch_bounds__(192) void dpb_kernel(const float* __restrict__ w_in,
                                                  const float* __restrict__ b_in,
                                                  const float* __restrict__ w_hid,
                                                  const float* __restrict__ b_hid,
                                                  const float* __restrict__ ln_g,
                                                  const float* __restrict__ ln_b,
                                                  const float* __restrict__ w_out,
                                                  const float* __restrict__ b_out)
{
    __shared__ float hbuf[16][DP];
    __shared__ float tmp[16][DP];
    __shared__ float mu_s[16], rs_s[16];
    const int j    = threadIdx.x;         // 0..191
    const int r0   = blockIdx.x * 16;
    const int warp = j >> 5, lane = j & 31;

    const float wi = w_in[j], bi = b_in[j];
#pragma unroll
    for (int r = 0; r < 16; r++) {
        float p = (float)(r0 + r) - 2047.0f;
        float sg = (p > 0.f) ? 1.f : ((p < 0.f) ? -1.f : 0.f);
        float pv = sg * logf(fabsf(p) + 1.f);
        tmp[r][j] = pv * wi + bi;
    }
    __syncthreads();

    for (int layer = 0; layer < 4; layer++) {
        for (int r = warp; r < 16; r += 6) {
            float s = 0.f, s2 = 0.f;
            for (int k = lane; k < DP; k += 32) {
                float v = tmp[r][k];
                s += v; s2 += v * v;
            }
#pragma unroll
            for (int off = 16; off > 0; off >>= 1) {
                s  += __shfl_xor_sync(0xffffffffu, s,  off);
                s2 += __shfl_xor_sync(0xffffffffu, s2, off);
            }
            if (lane == 0) {
                float mu = s * (1.0f / DP);
                float var = s2 * (1.0f / DP) - mu * mu;
                mu_s[r] = mu;
                rs_s[r] = rsqrtf(var + 1e-5f);
            }
        }
        __syncthreads();
        const float gj = ln_g[layer * DP + j], bj = ln_b[layer * DP + j];
#pragma unroll
        for (int r = 0; r < 16; r++) {
            float v = (tmp[r][j] - mu_s[r]) * rs_s[r] * gj + bj;
            hbuf[r][j] = v / (1.f + expf(-v));    // SiLU
        }
        __syncthreads();

        if (layer < 3) {
            float acc[16];
#pragma unroll
            for (int r = 0; r < 16; r++) acc[r] = 0.f;
            const float* Wp = w_hid + (size_t)layer * DP * DP + j;
            for (int k = 0; k < DP; k++) {
                float w = Wp[(size_t)k * DP];
#pragma unroll
                for (int r = 0; r < 16; r++) acc[r] = fmaf(hbuf[r][k], w, acc[r]);
            }
            const float bh = b_hid[layer * DP + j];
#pragma unroll
            for (int r = 0; r < 16; r++) tmp[r][j] = acc[r] + bh;
            __syncthreads();
        }
    }

    const int rr = j / 12, cc = j - rr * 12;
    float a = 0.f;
    for (int k = 0; k < DP; k++) a = fmaf(hbuf[rr][k], w_out[k * 12 + cc], a);
    const int row = r0 + rr;
    if (row < NPOS) g_vals[(size_t)row * HH + cc] = a + b_out[cc];
}

// =============================================================================
// Kernel 3: flash attention, 128 q x 64 k per tile, 256 threads, 8x4/thread,
// f32x2 FMAs.  Single-buffered K/V/bias tiles (103 KB smem) so TWO CTAs fit
// per SM — 16 warps/SM hides LDS/global latency better than prefetch did.
// =============================================================================
#define QS 132   // stride for 128-wide transposed tiles (Qs, Ps)
#define KS 68    // stride for 64-wide tiles (Ks, Vs)

__global__ __launch_bounds__(256, 2) void attn_kernel()
{
    extern __shared__ float sm[];
    float* Qs     = sm;                     // [64][132] transposed: Qs[d][m]
    float* Ps     = Qs + 64 * QS;           // [64][132] transposed: Ps[k][m]
    float* Ks     = Ps + 64 * QS;           // [64][68]  transposed: Ks[d][n]
    float* Vs     = Ks + 64 * KS;           // [64][68]  natural:    Vs[k][d]
    float* vals_s = Vs + 64 * KS;           // [192] bias diagonal slice

    const int bh = blockIdx.y;
    const int b  = bh / HH, h = bh - b * HH;
    const int q0 = blockIdx.x * 128;
    const float* Qg = g_q + (size_t)bh * NN * DH;
    const float* Kg = g_k + (size_t)bh * NN * DH;
    const float* Vg = g_v + (size_t)bh * NN * DH;

    const int tid = threadIdx.x;
    const int tx = tid & 15, ty = tid >> 4;
    const int sm_m  = tid >> 4;            // 0..15 base row for staging
    const int sm_c4 = (tid & 15) << 2;     // 0..60 col group for staging

    // ---- load Q tile (128x64) transposed; q already scaled by Dh^-0.5 ----
#pragma unroll
    for (int i = 0; i < 8; i++) {
        int m = sm_m + i * 16;
        float4 v = *reinterpret_cast<const float4*>(&Qg[(size_t)(q0 + m) * DH + sm_c4]);
        Qs[(sm_c4 + 0) * QS + m] = v.x;
        Qs[(sm_c4 + 1) * QS + m] = v.y;
        Qs[(sm_c4 + 2) * QS + m] = v.z;
        Qs[(sm_c4 + 3) * QS + m] = v.w;
    }

    float m_i[8], l_i[8];
    u64 oacc[8][2];
#pragma unroll
    for (int i = 0; i < 8; i++) {
        m_i[i] = -1e30f;
        l_i[i] = 0.f;
        oacc[i][0] = 0ULL;
        oacc[i][1] = 0ULL;
    }

    for (int kt = 0; kt < NN / 64; kt++) {
        const int kk0 = kt * 64;
        // buffer is free here: kt==0 trivially; kt>0 by the sync after PV below
        // stage K (transposed via regs), V (cp.async), bias slice
#pragma unroll
        for (int i = 0; i < 4; i++) {
            int m = sm_m + i * 16;
            float4 kv = *reinterpret_cast<const float4*>(&Kg[(size_t)(kk0 + m) * DH + sm_c4]);
            cpa16(&Vs[m * KS + sm_c4], &Vg[(size_t)(kk0 + m) * DH + sm_c4]);
            Ks[(sm_c4 + 0) * KS + m] = kv.x;
            Ks[(sm_c4 + 1) * KS + m] = kv.y;
            Ks[(sm_c4 + 2) * KS + m] = kv.z;
            Ks[(sm_c4 + 3) * KS + m] = kv.w;
        }
        cpa_commit();
        if (tid < 191) vals_s[tid] = g_vals[(size_t)(q0 - kk0 + 2047 - 63 + tid) * HH + h];
        cpa_wait0();
        __syncthreads();

        // S = Q @ K^T  (128x64), packed f32x2 accumulation
        u64 sacc[8][2];
#pragma unroll
        for (int i = 0; i < 8; i++) { sacc[i][0] = 0ULL; sacc[i][1] = 0ULL; }
#pragma unroll 4
        for (int d = 0; d < 64; d++) {
            float4 qa = *reinterpret_cast<const float4*>(&Qs[d * QS + ty * 8]);
            float4 qb = *reinterpret_cast<const float4*>(&Qs[d * QS + ty * 8 + 4]);
            float4 kb = *reinterpret_cast<const float4*>(&Ks[d * KS + tx * 4]);
            u64 bp0 = pk2(kb.x, kb.y), bp1 = pk2(kb.z, kb.w);
            float av[8] = {qa.x, qa.y, qa.z, qa.w, qb.x, qb.y, qb.z, qb.w};
#pragma unroll
            for (int i = 0; i < 8; i++) {
                u64 ap = pk2(av[i], av[i]);
                fma2(sacc[i][0], ap, bp0);
                fma2(sacc[i][1], ap, bp1);
            }
        }

        // + bias, online softmax (rows share 16 threads; shfl width 16)
#pragma unroll
        for (int i = 0; i < 8; i++) {
            float2 p0 = upk2(sacc[i][0]);
            float2 p1 = upk2(sacc[i][1]);
            float s0 = p0.x, s1 = p0.y, s2 = p1.x, s3 = p1.y;
            int moff = ty * 8 + i - tx * 4 + 63;
            s0 += vals_s[moff];
            s1 += vals_s[moff - 1];
            s2 += vals_s[moff - 2];
            s3 += vals_s[moff - 3];
            float rm = fmaxf(fmaxf(s0, s1), fmaxf(s2, s3));
#pragma unroll
            for (int off = 8; off > 0; off >>= 1)
                rm = fmaxf(rm, __shfl_xor_sync(0xffffffffu, rm, off, 16));
            float mnew  = fmaxf(m_i[i], rm);
            float alpha = __expf(m_i[i] - mnew);
            s0 = __expf(s0 - mnew);
            s1 = __expf(s1 - mnew);
            s2 = __expf(s2 - mnew);
            s3 = __expf(s3 - mnew);
            float rsum = s0 + s1 + s2 + s3;
#pragma unroll
            for (int off = 8; off > 0; off >>= 1)
                rsum += __shfl_xor_sync(0xffffffffu, rsum, off, 16);
            l_i[i] = l_i[i] * alpha + rsum;
            m_i[i] = mnew;
            u64 alp = pk2(alpha, alpha);
            mul2(oacc[i][0], alp);
            mul2(oacc[i][1], alp);
            // write P transposed for the PV GEMM
            Ps[(tx * 4 + 0) * QS + ty * 8 + i] = s0;
            Ps[(tx * 4 + 1) * QS + ty * 8 + i] = s1;
            Ps[(tx * 4 + 2) * QS + ty * 8 + i] = s2;
            Ps[(tx * 4 + 3) * QS + ty * 8 + i] = s3;
        }
        __syncthreads();   // Ps visible to all warps

        // O += P @ V  (128x64 += 128x64 @ 64x64), packed f32x2
#pragma unroll 4
        for (int k = 0; k < 64; k++) {
            float4 pa = *reinterpret_cast<const float4*>(&Ps[k * QS + ty * 8]);
            float4 pb = *reinterpret_cast<const float4*>(&Ps[k * QS + ty * 8 + 4]);
            float4 vb = *reinterpret_cast<const float4*>(&Vs[k * KS + tx * 4]);
            u64 bp0 = pk2(vb.x, vb.y), bp1 = pk2(vb.z, vb.w);
            float av[8] = {pa.x, pa.y, pa.z, pa.w, pb.x, pb.y, pb.z, pb.w};
#pragma unroll
            for (int i = 0; i < 8; i++) {
                u64 ap = pk2(av[i], av[i]);
                fma2(oacc[i][0], ap, bp0);
                fma2(oacc[i][1], ap, bp1);
            }
        }
        __syncthreads();   // done reading Ks/Vs/vals before next stage
    }

    // normalize and store to [b,n,h*64+d] for the output projection
#pragma unroll
    for (int i = 0; i < 8; i++) {
        float inv = 1.0f / l_i[i];
        float2 v0 = upk2(oacc[i][0]);
        float2 v1 = upk2(oacc[i][1]);
        float4 o;
        o.x = v0.x * inv;
        o.y = v0.y * inv;
        o.z = v1.x * inv;
        o.w = v1.y * inv;
        size_t row = (size_t)b * NN + q0 + ty * 8 + i;
        *reinterpret_cast<float4*>(&g_o[row * DD + h * DH + tx * 4]) = o;
    }
}

// =============================================================================
extern "C" void kernel_launch(void* const* d_in, const int* in_sizes, int n_in,
                              void* d_out, int out_size)
{
    const float* x         = (const float*)d_in[0];
    const float* qkv_w     = (const float*)d_in[1];
    const float* qkv_b     = (const float*)d_in[2];
    const float* out_w     = (const float*)d_in[3];
    const float* out_b     = (const float*)d_in[4];
    const float* dpb_w_in  = (const float*)d_in[5];
    const float* dpb_b_in  = (const float*)d_in[6];
    const float* dpb_w_hid = (const float*)d_in[7];
    const float* dpb_b_hid = (const float*)d_in[8];
    const float* dpb_ln_g  = (const float*)d_in[9];
    const float* dpb_ln_b  = (const float*)d_in[10];
    const float* dpb_w_out = (const float*)d_in[11];
    const float* dpb_b_out = (const float*)d_in[12];
    float* out = (float*)d_out;

    // single-buffered attention smem: 2*64*132 + 2*64*68 + 192 floats = ~103 KB
    const int attn_smem =
        (2 * 64 * QS + 2 * 64 * KS + 192) * (int)sizeof(float);
    cudaFuncSetAttribute(attn_kernel, cudaFuncAttributeMaxDynamicSharedMemorySize,
                         attn_smem);

    dpb_kernel<<<256, 192>>>(dpb_w_in, dpb_b_in, dpb_w_hid, dpb_b_hid,
                             dpb_ln_g, dpb_ln_b, dpb_w_out, dpb_b_out);
    big_gemm<<<dim3(18, 32), 256>>>(x, qkv_w, 2304, 0, qkv_b, nullptr);
    attn_kernel<<<dim3(16, 24), 256, attn_smem>>>();
    big_gemm<<<dim3(6, 32), 256>>>(nullptr, out_w, 768, 1, out_b, out);
}